// round 11
// baseline (speedup 1.0000x reference)
#include <cuda_runtime.h>
#include <cuda_fp16.h>
#include <stdint.h>

#define BB 32
#define NQ 1024
#define GSZ 1024
#define ED 128
#define NH 8
#define HD 16
#define MROWS (BB*NQ)

__device__ __half g_Qhi[(size_t)BB*NH*NQ*HD];
__device__ __half g_Qlo[(size_t)BB*NH*NQ*HD];
__device__ __half g_Khi[(size_t)BB*NH*GSZ*HD];
__device__ __half g_Vt [(size_t)BB*NH*HD*GSZ];   // [b,h,e,g]
__device__ __half g_HPhi[(size_t)MROWS*ED];
__device__ __half g_HPlo[(size_t)MROWS*ED];
__device__ __half g_Whi[4*128*128];              // [mode][n][k]
__device__ __half g_Wlo[4*128*128];
__device__ uint32_t g_mbits[(size_t)BB*NQ*32];
__device__ int g_mdtype;

// ======================== helpers ========================
__device__ __forceinline__ float ex2f(float x) {
    float r; asm("ex2.approx.f32 %0, %1;" : "=f"(r) : "f"(x));
    return r;
}
__device__ __forceinline__ uint32_t packh2_u(__half a, __half b) {
    __half2 h; h.x = a; h.y = b;
    return *(uint32_t*)&h;
}
__device__ __forceinline__ uint32_t packf2(float a, float b) {
    __half2 h = __floats2half2_rn(a, b);
    return *(uint32_t*)&h;
}
__device__ __forceinline__ uint32_t h2u(__half2 h) { return *(uint32_t*)&h; }
__device__ __forceinline__ uint32_t smem_u32(const void* p) {
    uint32_t a;
    asm("{ .reg .u64 t; cvta.to.shared.u64 t, %1; cvt.u32.u64 %0, t; }" : "=r"(a) : "l"(p));
    return a;
}
__device__ __forceinline__ void mma_k16(float* c, const uint32_t* a, const uint32_t* b) {
    asm volatile("mma.sync.aligned.m16n8k16.row.col.f32.f16.f16.f32 "
        "{%0,%1,%2,%3}, {%4,%5,%6,%7}, {%8,%9}, {%0,%1,%2,%3};"
        : "+f"(c[0]), "+f"(c[1]), "+f"(c[2]), "+f"(c[3])
        : "r"(a[0]), "r"(a[1]), "r"(a[2]), "r"(a[3]), "r"(b[0]), "r"(b[1]));
}
#define LDSM_X4(r0, r1, r2, r3, addr) \
    asm volatile("ldmatrix.sync.aligned.m8n8.x4.shared.b16 {%0,%1,%2,%3}, [%4];" \
        : "=r"(r0), "=r"(r1), "=r"(r2), "=r"(r3) : "r"(addr))
#define CP_ASYNC16(dst, src) \
    asm volatile("cp.async.cg.shared.global [%0], [%1], 16;" :: "r"(dst), "l"(src))
#define CP_COMMIT() asm volatile("cp.async.commit_group;" ::: "memory")
#define CP_WAIT0()  asm volatile("cp.async.wait_group 0;" ::: "memory")

// ======================== mask dtype detect ========================
__global__ void detect_mask_kernel(const unsigned int* __restrict__ m)
{
    __shared__ int sf32, sgt1;
    if (threadIdx.x == 0) { sf32 = 0; sgt1 = 0; }
    __syncthreads();
    for (int i = threadIdx.x; i < 2048; i += blockDim.x) {
        unsigned int w = m[i];
        if (w == 0x3F800000u) sf32 = 1;
        else if (w > 1u) sgt1 = 1;
    }
    __syncthreads();
    if (threadIdx.x == 0) g_mdtype = sf32 ? 2 : (sgt1 ? 0 : 1);
}

__device__ __forceinline__ uint32_t pack32(const void* m, int dt, size_t w)
{
    uint32_t bits = 0;
    if (dt == 0) {
        const uchar4* p = (const uchar4*)m + w * 8;
        #pragma unroll
        for (int i = 0; i < 8; i++) {
            uchar4 v = p[i];
            bits |= (uint32_t)(v.x != 0) << (i*4)
                  | (uint32_t)(v.y != 0) << (i*4+1)
                  | (uint32_t)(v.z != 0) << (i*4+2)
                  | (uint32_t)(v.w != 0) << (i*4+3);
        }
    } else if (dt == 1) {
        const int4* p = (const int4*)m + w * 8;
        #pragma unroll
        for (int i = 0; i < 8; i++) {
            int4 v = p[i];
            bits |= (uint32_t)(v.x != 0) << (i*4)
                  | (uint32_t)(v.y != 0) << (i*4+1)
                  | (uint32_t)(v.z != 0) << (i*4+2)
                  | (uint32_t)(v.w != 0) << (i*4+3);
        }
    } else {
        const float4* p = (const float4*)m + w * 8;
        #pragma unroll
        for (int i = 0; i < 8; i++) {
            float4 v = p[i];
            bits |= (uint32_t)(v.x != 0.f) << (i*4)
                  | (uint32_t)(v.y != 0.f) << (i*4+1)
                  | (uint32_t)(v.z != 0.f) << (i*4+2)
                  | (uint32_t)(v.w != 0.f) << (i*4+3);
        }
    }
    return bits;
}

// ======================== W pre-split (C folded into Wq) ========================
__global__ __launch_bounds__(256) void split_w_kernel(
    const float* __restrict__ Wq, const float* __restrict__ Wk,
    const float* __restrict__ Wv, const float* __restrict__ Wout)
{
    int mode = blockIdx.y;
    const float* W = (mode == 0) ? Wq : (mode == 1 ? Wk : (mode == 2 ? Wv : Wout));
    int idx = blockIdx.x * 256 + threadIdx.x;
    int n = idx >> 7, k = idx & 127;
    float w = (mode < 3)
        ? W[(size_t)(n >> 4) * (ED * HD) + (size_t)k * HD + (n & 15)]
        : W[(size_t)k * ED + n];
    if (mode == 0) w *= 0.36067376022224085f;   // 0.25 * log2(e)
    __half hh = __float2half_rn(w);
    g_Whi[mode * 16384 + idx] = hh;
    g_Wlo[mode * 16384 + idx] = __float2half_rn(w - __half2float(hh));
}

// ======================== pipelined tensor-core GEMM (+bitpack slice) ========
#define CH 5120
#define GEMM_SMEM (8 * CH * 2)

__global__ __launch_bounds__(256, 2) void gemm_mma_kernel(
    const float* __restrict__ q, const float* __restrict__ h,
    const void* __restrict__ mask_raw, float* __restrict__ out, int mode_base)
{
    // y==3 in the 4-slice launch: bitpack the mask (DRAM-bound filler blocks)
    if (blockIdx.y == 3 && gridDim.y == 4) {
        int dt = g_mdtype;
        size_t base = (size_t)blockIdx.x * 4096 + threadIdx.x;
        #pragma unroll 4
        for (int it = 0; it < 16; it++) {
            size_t w = base + (size_t)it * 256;
            g_mbits[w] = pack32(mask_raw, dt, w);
        }
        return;
    }

    extern __shared__ __align__(16) __half dsm[];
    __half* sAhi = dsm;            // [2][CH]
    __half* sAlo = dsm + 2*CH;
    __half* sWhi = dsm + 4*CH;
    __half* sWlo = dsm + 6*CH;

    int mode = mode_base + blockIdx.y;
    const float* A = (mode == 0) ? q : h;
    bool full3 = (mode == 0) || (mode == 3);   // 3-term hi/lo (Q, out-proj)

    int tid = threadIdx.x, wid = tid >> 5, lane = tid & 31;
    int row0 = blockIdx.x * 128;
    int wr = wid & 1, wc = wid >> 1;
    int mi = lane >> 3, ri = lane & 7;

    float c[4][4][4] = {};

    uint32_t a_lo = (uint32_t)(((lane & 15) * 40 + (lane >> 4) * 8) * 2);
    uint32_t b_lo = (uint32_t)((((mi >> 1) * 8 + ri) * 40 + (mi & 1) * 8) * 2);
    uint32_t sAhi_b = smem_u32(sAhi), sAlo_b = smem_u32(sAlo);
    uint32_t sWhi_b = smem_u32(sWhi), sWlo_b = smem_u32(sWlo);

    int r_st = tid >> 1, kh_st = (tid & 1) * 16;
    uint32_t st_d = (uint32_t)((r_st * 40 + kh_st) * 2);
    const __half* Whi = g_Whi + mode * 16384;
    const __half* Wlo = g_Wlo + mode * 16384;

    // prologue: chunk 0
    {
        const __half* ws = Whi + r_st * 128 + kh_st;
        CP_ASYNC16(sWhi_b + st_d,      ws);
        CP_ASYNC16(sWhi_b + st_d + 16, ws + 8);
        if (full3) {
            const __half* wl = Wlo + r_st * 128 + kh_st;
            CP_ASYNC16(sWlo_b + st_d,      wl);
            CP_ASYNC16(sWlo_b + st_d + 16, wl + 8);
        }
        if (mode == 3) {
            const __half* as = g_HPhi + (size_t)(row0 + r_st) * ED + kh_st;
            const __half* al = g_HPlo + (size_t)(row0 + r_st) * ED + kh_st;
            CP_ASYNC16(sAhi_b + st_d,      as);
            CP_ASYNC16(sAhi_b + st_d + 16, as + 8);
            CP_ASYNC16(sAlo_b + st_d,      al);
            CP_ASYNC16(sAlo_b + st_d + 16, al + 8);
        } else {
            const float* ap = A + (size_t)(row0 + r_st) * ED + kh_st;
            #pragma unroll
            for (int j4 = 0; j4 < 4; j4++) {
                float4 v = *(const float4*)(ap + j4 * 4);
                float vv[4] = {v.x, v.y, v.z, v.w};
                __half hi[4], lo[4];
                #pragma unroll
                for (int u = 0; u < 4; u++) {
                    hi[u] = __float2half_rn(vv[u]);
                    lo[u] = __float2half_rn(vv[u] - __half2float(hi[u]));
                }
                *(uint2*)(sAhi + r_st*40 + kh_st + j4*4) = *(uint2*)hi;
                *(uint2*)(sAlo + r_st*40 + kh_st + j4*4) = *(uint2*)lo;
            }
        }
        CP_COMMIT();
    }

    for (int kc = 0; kc < 4; kc++) {
        CP_WAIT0();
        __syncthreads();
        int p = kc & 1;
        uint32_t off_p = (uint32_t)(p * CH * 2);

        float4 rA[4];
        if (kc < 3) {
            int pn = p ^ 1;
            uint32_t off_n = (uint32_t)(pn * CH * 2);
            const __half* ws = Whi + r_st * 128 + (kc+1)*32 + kh_st;
            CP_ASYNC16(sWhi_b + off_n + st_d,      ws);
            CP_ASYNC16(sWhi_b + off_n + st_d + 16, ws + 8);
            if (full3) {
                const __half* wl = Wlo + r_st * 128 + (kc+1)*32 + kh_st;
                CP_ASYNC16(sWlo_b + off_n + st_d,      wl);
                CP_ASYNC16(sWlo_b + off_n + st_d + 16, wl + 8);
            }
            if (mode == 3) {
                const __half* as = g_HPhi + (size_t)(row0 + r_st) * ED + (kc+1)*32 + kh_st;
                const __half* al = g_HPlo + (size_t)(row0 + r_st) * ED + (kc+1)*32 + kh_st;
                CP_ASYNC16(sAhi_b + off_n + st_d,      as);
                CP_ASYNC16(sAhi_b + off_n + st_d + 16, as + 8);
                CP_ASYNC16(sAlo_b + off_n + st_d,      al);
                CP_ASYNC16(sAlo_b + off_n + st_d + 16, al + 8);
            } else {
                const float* ap = A + (size_t)(row0 + r_st) * ED + (kc+1)*32 + kh_st;
                #pragma unroll
                for (int j4 = 0; j4 < 4; j4++) rA[j4] = *(const float4*)(ap + j4 * 4);
            }
            CP_COMMIT();
        }

        #pragma unroll
        for (int ks = 0; ks < 2; ks++) {
            uint32_t koff = (uint32_t)(ks * 32);
            uint32_t bhi[2][4], blo[2][4];
            #pragma unroll
            for (int nb = 0; nb < 2; nb++) {
                uint32_t no = (uint32_t)((wc*32 + nb*16) * 80) + koff + b_lo + off_p;
                LDSM_X4(bhi[nb][0], bhi[nb][1], bhi[nb][2], bhi[nb][3], sWhi_b + no);
                if (full3)
                    LDSM_X4(blo[nb][0], blo[nb][1], blo[nb][2], blo[nb][3], sWlo_b + no);
            }
            #pragma unroll
            for (int mb = 0; mb < 4; mb++) {
                uint32_t ro = (uint32_t)((wr*64 + mb*16) * 80) + koff + a_lo + off_p;
                uint32_t ahi[4], alo[4];
                LDSM_X4(ahi[0], ahi[1], ahi[2], ahi[3], sAhi_b + ro);
                LDSM_X4(alo[0], alo[1], alo[2], alo[3], sAlo_b + ro);
                #pragma unroll
                for (int ns = 0; ns < 4; ns++) {
                    const uint32_t* bh = &bhi[ns >> 1][(ns & 1) * 2];
                    mma_k16(c[mb][ns], ahi, bh);
                    mma_k16(c[mb][ns], alo, bh);
                    if (full3) {
                        const uint32_t* bl = &blo[ns >> 1][(ns & 1) * 2];
                        mma_k16(c[mb][ns], ahi, bl);
                    }
                }
            }
        }

        if (kc < 3 && mode < 3) {
            int pn = p ^ 1;
            #pragma unroll
            for (int j4 = 0; j4 < 4; j4++) {
                float vv[4] = {rA[j4].x, rA[j4].y, rA[j4].z, rA[j4].w};
                __half hi[4], lo[4];
                #pragma unroll
                for (int u = 0; u < 4; u++) {
                    hi[u] = __float2half_rn(vv[u]);
                    lo[u] = __float2half_rn(vv[u] - __half2float(hi[u]));
                }
                *(uint2*)(sAhi + pn*CH + r_st*40 + kh_st + j4*4) = *(uint2*)hi;
                *(uint2*)(sAlo + pn*CH + r_st*40 + kh_st + j4*4) = *(uint2*)lo;
            }
        }
    }

    // epilogue
    int g = lane >> 2, t = lane & 3;
    #pragma unroll
    for (int mb = 0; mb < 4; mb++) {
        int grow = row0 + wr*64 + mb*16 + g;
        #pragma unroll
        for (int ns = 0; ns < 4; ns++) {
            int col = wc*32 + ns*8 + 2*t;
            float* cc = c[mb][ns];
            if (mode == 3) {
                *(float2*)(out + (size_t)grow * ED + col) = make_float2(cc[0], cc[1]);
                *(float2*)(out + (size_t)(grow + 8) * ED + col) = make_float2(cc[2], cc[3]);
            } else {
                int head = col >> 4, e = col & 15;
                int b = grow >> 10, n = grow & 1023;
                if (mode == 2) {
                    __half* vt = g_Vt + ((size_t)(b*NH + head) * 16 + e) * 1024;
                    vt[n]            = __float2half_rn(cc[0]);
                    vt[1024 + n]     = __float2half_rn(cc[1]);
                    vt[n + 8]        = __float2half_rn(cc[2]);
                    vt[1024 + n + 8] = __float2half_rn(cc[3]);
                } else {
                    __half* HI = (mode == 0) ? g_Qhi : g_Khi;
                    size_t base0 = ((size_t)(b*NH + head) * 1024 + n) * 16 + e;
                    size_t base1 = base0 + 8 * 16;
                    __half h0 = __float2half_rn(cc[0]), h1 = __float2half_rn(cc[1]);
                    __half h2 = __float2half_rn(cc[2]), h3 = __float2half_rn(cc[3]);
                    *(uint32_t*)(HI + base0) = packh2_u(h0, h1);
                    *(uint32_t*)(HI + base1) = packh2_u(h2, h3);
                    if (mode == 0) {
                        *(uint32_t*)(g_Qlo + base0) =
                            packf2(cc[0] - __half2float(h0), cc[1] - __half2float(h1));
                        *(uint32_t*)(g_Qlo + base1) =
                            packf2(cc[2] - __half2float(h2), cc[3] - __half2float(h3));
                    }
                }
            }
        }
    }
}

// ======================== flash attention ========================
__device__ __forceinline__ void store_hl(__half* HI, __half* LO, size_t off,
                                         float x, float y) {
    __half hx = __float2half_rn(x), hy = __float2half_rn(y);
    *(uint32_t*)(HI + off) = packh2_u(hx, hy);
    *(uint32_t*)(LO + off) = packf2(x - __half2float(hx), y - __half2float(hy));
}

__global__ __launch_bounds__(256, 2) void attn_mma_kernel(
    const __half* __restrict__ Qhi, const __half* __restrict__ Qlo,
    const __half* __restrict__ Khig, const __half* __restrict__ Vtg,
    const uint32_t* __restrict__ Mbits)
{
    __shared__ __align__(16) __half sKhi[2][128*24];
    __shared__ __align__(16) __half sVt [2][16*136];

    int tid = threadIdx.x, wid = tid >> 5, lane = tid & 31;
    int g = lane >> 2, t = lane & 3;
    int hd = blockIdx.x, q0 = blockIdx.y * 128, b = blockIdx.z;

    const __half* Kh = Khig + (size_t)(b*NH+hd) * GSZ * HD;
    const __half* Vg = Vtg  + (size_t)(b*NH+hd) * HD * GSZ;

    int k_row = tid >> 1, k_half = tid & 1;
    int v_e = tid >> 4, v_seg = tid & 15;
    uint32_t dKhi[2], dVt[2];
    #pragma unroll
    for (int bb = 0; bb < 2; bb++) {
        dKhi[bb] = smem_u32(&sKhi[bb][0]) + k_row * 48 + k_half * 16;
        dVt[bb]  = smem_u32(&sVt[bb][0])  + v_e * 272 + v_seg * 16;
    }

    int mi = lane >> 3, ri = lane & 7;
    uint32_t k_lb = (uint32_t)((((mi >> 1) * 8 + ri) * 24 + (mi & 1) * 8) * 2);
    uint32_t v_lb = (uint32_t)((((mi & 1) * 8 + ri) * 136 + (mi >> 1) * 8) * 2);

    {
        const __half* s1 = Kh + (size_t)k_row * 16 + k_half * 8;
        const __half* s3 = Vg + (size_t)v_e * GSZ + v_seg * 8;
        CP_ASYNC16(dKhi[0], s1); CP_ASYNC16(dVt[0], s3);
        CP_COMMIT();
    }

    uint32_t qhi[4], qlo[4];
    {
        size_t qb = ((size_t)(b*NH+hd) * NQ + q0 + wid*16) * 16;
        #pragma unroll
        for (int i = 0; i < 4; i++) {
            int r = g + (i & 1) * 8;
            int cix = 2*t + (i >> 1) * 8;
            qhi[i] = *(const uint32_t*)(Qhi + qb + r*16 + cix);
            qlo[i] = *(const uint32_t*)(Qlo + qb + r*16 + cix);
        }
    }

    int rg0 = q0 + wid*16 + g;
    const uint32_t* mb0p = Mbits + ((size_t)b * NQ + rg0) * 32;
    const uint32_t* mb1p = mb0p + 8 * 32;

    const uint32_t ones2[2] = {0x3C003C00u, 0x3C003C00u};
    float o[8] = {};
    float lacc[4] = {};
    float m0 = -1e30f, m1 = -1e30f;

    for (int t8 = 0; t8 < 8; t8++) {
        CP_WAIT0();
        __syncthreads();
        int bb = t8 & 1;

        if (t8 < 7) {
            int k0n = (t8 + 1) * 128;
            const __half* s1 = Kh + (size_t)(k0n + k_row) * 16 + k_half * 8;
            const __half* s3 = Vg + (size_t)v_e * GSZ + k0n + v_seg * 8;
            CP_ASYNC16(dKhi[bb ^ 1], s1); CP_ASYNC16(dVt[bb ^ 1], s3);
            CP_COMMIT();
        }

        uint4 mw0 = *(const uint4*)(mb0p + t8 * 4);
        uint4 mw1 = *(const uint4*)(mb1p + t8 * 4);

        uint32_t khb = smem_u32(&sKhi[bb][0]) + k_lb;
        uint32_t vtb = smem_u32(&sVt[bb][0]) + v_lb;

        #pragma unroll
        for (int hf = 0; hf < 2; hf++) {
            float s[8][4];
            #pragma unroll
            for (int kc = 0; kc < 8; kc++)
                s[kc][0] = s[kc][1] = s[kc][2] = s[kc][3] = 0.f;
            #pragma unroll
            for (int j = 0; j < 4; j++) {
                uint32_t kh[4];
                uint32_t off = (uint32_t)((hf*64 + j*16) * 48);
                LDSM_X4(kh[0], kh[1], kh[2], kh[3], khb + off);
                mma_k16(s[2*j],   qhi, kh);
                mma_k16(s[2*j],   qlo, kh);
                mma_k16(s[2*j+1], qhi, kh+2);
                mma_k16(s[2*j+1], qlo, kh+2);
            }
            float tm0 = -1e30f, tm1 = -1e30f;
            #pragma unroll
            for (int kc = 0; kc < 8; kc++) {
                tm0 = fmaxf(tm0, fmaxf(s[kc][0], s[kc][1]));
                tm1 = fmaxf(tm1, fmaxf(s[kc][2], s[kc][3]));
            }
            tm0 = fmaxf(tm0, __shfl_xor_sync(0xffffffffu, tm0, 1));
            tm0 = fmaxf(tm0, __shfl_xor_sync(0xffffffffu, tm0, 2));
            tm1 = fmaxf(tm1, __shfl_xor_sync(0xffffffffu, tm1, 1));
            tm1 = fmaxf(tm1, __shfl_xor_sync(0xffffffffu, tm1, 2));

            float mn0 = fmaxf(m0, tm0);
            float mn1 = fmaxf(m1, tm1);
            float f0 = ex2f(m0 - mn0), f1 = ex2f(m1 - mn1);
            m0 = mn0; m1 = mn1;
            o[0] *= f0; o[1] *= f0; o[4] *= f0; o[5] *= f0;
            o[2] *= f1; o[3] *= f1; o[6] *= f1; o[7] *= f1;
            lacc[0] *= f0; lacc[2] *= f1;

            uint32_t w0a = hf ? mw0.z : mw0.x, w0b = hf ? mw0.w : mw0.y;
            uint32_t w1a = hf ? mw1.z : mw1.x, w1b = hf ? mw1.w : mw1.y;

            #pragma unroll
            for (int jj = 0; jj < 4; jj++) {
                uint32_t v0e, v1e, v0o, v1o;
                LDSM_X4(v0e, v1e, v0o, v1o, vtb + (uint32_t)((hf*64 + jj*16) * 2));
                uint32_t a[4];
                #pragma unroll
                for (int q2 = 0; q2 < 2; q2++) {
                    int kc = 2*jj + q2;
                    uint32_t wa = (kc < 4) ? w0a : w0b;
                    uint32_t wb = (kc < 4) ? w1a : w1b;
                    int sh = (kc & 3) * 8 + 2*t;
                    uint32_t p0 = (wa >> sh) & 3u;
                    uint32_t p1 = (wb >> sh) & 3u;
                    uint32_t km0 = ((p0 & 1) ? 0u : 0xFFFFu) | ((p0 & 2) ? 0u : 0xFFFF0000u);
                    uint32_t km1 = ((p1 & 1) ? 0u : 0xFFFFu) | ((p1 & 2) ? 0u : 0xFFFF0000u);
                    __half2 d01 = __floats2half2_rn(s[kc][0] - mn0, s[kc][1] - mn0);
                    __half2 d23 = __floats2half2_rn(s[kc][2] - mn1, s[kc][3] - mn1);
                    a[2*q2]     = h2u(h2exp2(d01)) & km0;
                    a[2*q2 + 1] = h2u(h2exp2(d23)) & km1;
                }
                uint32_t be[2] = {v0e, v0o};
                uint32_t bo[2] = {v1e, v1o};
                mma_k16(o,     a, be);
                mma_k16(o + 4, a, bo);
                mma_k16(lacc,  a, ones2);
            }
        }
        __syncthreads();
    }

    float inv0 = 1.f / lacc[0], inv1 = 1.f / lacc[2];

    size_t r0 = ((size_t)b*NQ + q0 + wid*16 + g) * ED + hd * HD;
    size_t r1 = r0 + 8 * ED;
    store_hl(g_HPhi, g_HPlo, r0 + 2*t,     o[0]*inv0, o[1]*inv0);
    store_hl(g_HPhi, g_HPlo, r0 + 8 + 2*t, o[4]*inv0, o[5]*inv0);
    store_hl(g_HPhi, g_HPlo, r1 + 2*t,     o[2]*inv1, o[3]*inv1);
    store_hl(g_HPhi, g_HPlo, r1 + 8 + 2*t, o[6]*inv1, o[7]*inv1);
}

// ======================== launch ========================
extern "C" void kernel_launch(void* const* d_in, const int* in_sizes, int n_in,
                              void* d_out, int out_size)
{
    const float* q = (const float*)d_in[0];
    const float* h = (const float*)d_in[1];
    const void*  mask_raw = d_in[2];
    const float* Wq = (const float*)d_in[3];
    const float* Wk = (const float*)d_in[4];
    const float* Wv = (const float*)d_in[5];
    const float* Wout = (const float*)d_in[6];
    float* out = (float*)d_out;

    __half *Qhi, *Qlo, *Khi, *Vt;
    uint32_t* MB;
    cudaGetSymbolAddress((void**)&Qhi, g_Qhi);
    cudaGetSymbolAddress((void**)&Qlo, g_Qlo);
    cudaGetSymbolAddress((void**)&Khi, g_Khi);
    cudaGetSymbolAddress((void**)&Vt,  g_Vt);
    cudaGetSymbolAddress((void**)&MB,  g_mbits);

    cudaFuncSetAttribute(gemm_mma_kernel,
                         cudaFuncAttributeMaxDynamicSharedMemorySize, GEMM_SMEM);

    detect_mask_kernel<<<1, 256>>>((const unsigned int*)mask_raw);
    split_w_kernel<<<dim3(64, 4), 256>>>(Wq, Wk, Wv, Wout);

    // modes 0..2 (QKV) + slice y=3 does mask bitpack (DRAM-bound filler)
    gemm_mma_kernel<<<dim3(MROWS / 128, 4), 256, GEMM_SMEM>>>(q, h, mask_raw, out, 0);

    dim3 grid(NH, NQ / 128, BB);
    attn_mma_kernel<<<grid, 256>>>(Qhi, Qlo, Khi, Vt, MB);

    // out projection (mode 3; gridDim.y==1 so no bitpack slice)
    gemm_mma_kernel<<<dim3(MROWS / 128, 1), 256, GEMM_SMEM>>>(q, h, mask_raw, out, 3);
}

// round 14
// speedup vs baseline: 1.0669x; 1.0669x over previous
#include <cuda_runtime.h>
#include <cuda_fp16.h>
#include <stdint.h>

#define BB 32
#define NQ 1024
#define GSZ 1024
#define ED 128
#define NH 8
#define HD 16
#define MROWS (BB*NQ)

__device__ __half g_Qhi[(size_t)BB*NH*NQ*HD];
__device__ __half g_Qlo[(size_t)BB*NH*NQ*HD];
__device__ __half g_Khi[(size_t)BB*NH*GSZ*HD];
__device__ __half g_Vt [(size_t)BB*NH*HD*GSZ];   // [b,h,e,g]
__device__ __half g_HPhi[(size_t)MROWS*ED];
__device__ __half g_HPlo[(size_t)MROWS*ED];
__device__ __half g_Whi[4*128*128];              // [mode][n][k]
__device__ __half g_Wlo[4*128*128];
__device__ uint32_t g_mbits[(size_t)BB*NQ*32];
__device__ int g_mdtype;

// ======================== helpers ========================
__device__ __forceinline__ float ex2f(float x) {
    float r; asm("ex2.approx.f32 %0, %1;" : "=f"(r) : "f"(x));
    return r;
}
__device__ __forceinline__ uint32_t packh2_u(__half a, __half b) {
    __half2 h; h.x = a; h.y = b;
    return *(uint32_t*)&h;
}
__device__ __forceinline__ uint32_t packf2(float a, float b) {
    __half2 h = __floats2half2_rn(a, b);
    return *(uint32_t*)&h;
}
__device__ __forceinline__ uint32_t h2u(__half2 h) { return *(uint32_t*)&h; }
__device__ __forceinline__ uint32_t smem_u32(const void* p) {
    uint32_t a;
    asm("{ .reg .u64 t; cvta.to.shared.u64 t, %1; cvt.u32.u64 %0, t; }" : "=r"(a) : "l"(p));
    return a;
}
__device__ __forceinline__ void mma_k16(float* c, const uint32_t* a, const uint32_t* b) {
    asm volatile("mma.sync.aligned.m16n8k16.row.col.f32.f16.f16.f32 "
        "{%0,%1,%2,%3}, {%4,%5,%6,%7}, {%8,%9}, {%0,%1,%2,%3};"
        : "+f"(c[0]), "+f"(c[1]), "+f"(c[2]), "+f"(c[3])
        : "r"(a[0]), "r"(a[1]), "r"(a[2]), "r"(a[3]), "r"(b[0]), "r"(b[1]));
}
#define LDSM_X4(r0, r1, r2, r3, addr) \
    asm volatile("ldmatrix.sync.aligned.m8n8.x4.shared.b16 {%0,%1,%2,%3}, [%4];" \
        : "=r"(r0), "=r"(r1), "=r"(r2), "=r"(r3) : "r"(addr))
#define CP_ASYNC16(dst, src) \
    asm volatile("cp.async.cg.shared.global [%0], [%1], 16;" :: "r"(dst), "l"(src))
#define CP_COMMIT() asm volatile("cp.async.commit_group;" ::: "memory")
#define CP_WAIT0()  asm volatile("cp.async.wait_group 0;" ::: "memory")

// nonzero-byte -> 4-bit nibble (b0 at bit0 .. b3 at bit3)
__device__ __forceinline__ uint32_t nz4(uint32_t w) {
    uint32_t nz = (((w & 0x7F7F7F7Fu) + 0x7F7F7F7Fu) | w) & 0x80808080u;
    return (((nz >> 7) * 0x01020408u) >> 24) & 0xFu;
}

// ======================== W pre-split (+ mask dtype detect slice) ========
__global__ __launch_bounds__(256) void split_w_kernel(
    const float* __restrict__ Wq, const float* __restrict__ Wk,
    const float* __restrict__ Wv, const float* __restrict__ Wout,
    const unsigned int* __restrict__ mask_raw)
{
    int mode = blockIdx.y;
    if (mode == 4) {                       // detect slice: one block scans head of mask
        if (blockIdx.x != 0) return;
        __shared__ int sf32, sgt1;
        if (threadIdx.x == 0) { sf32 = 0; sgt1 = 0; }
        __syncthreads();
        for (int i = threadIdx.x; i < 2048; i += blockDim.x) {
            unsigned int w = mask_raw[i];
            if (w == 0x3F800000u) sf32 = 1;
            else if (w > 1u) sgt1 = 1;
        }
        __syncthreads();
        if (threadIdx.x == 0) g_mdtype = sf32 ? 2 : (sgt1 ? 0 : 1);
        return;
    }
    const float* W = (mode == 0) ? Wq : (mode == 1 ? Wk : (mode == 2 ? Wv : Wout));
    int idx = blockIdx.x * 256 + threadIdx.x;
    int n = idx >> 7, k = idx & 127;
    float w = (mode < 3)
        ? W[(size_t)(n >> 4) * (ED * HD) + (size_t)k * HD + (n & 15)]
        : W[(size_t)k * ED + n];
    if (mode == 0) w *= 0.36067376022224085f;   // 0.25 * log2(e)
    __half hh = __float2half_rn(w);
    g_Whi[mode * 16384 + idx] = hh;
    g_Wlo[mode * 16384 + idx] = __float2half_rn(w - __half2float(hh));
}

// ======================== mask bitpack (vectorized) ========================
__global__ __launch_bounds__(256) void bitpack_mask_kernel(const void* __restrict__ m)
{
    int dt = g_mdtype;
    size_t gt = (size_t)blockIdx.x * 256 + threadIdx.x;
    if (dt == 0) {
        // uint8: thread packs 128 bytes -> 4 output words
        if (gt >= (size_t)BB*NQ*32 / 4) return;
        const uint4* p = (const uint4*)m + gt * 8;
        #pragma unroll
        for (int o = 0; o < 4; o++) {
            uint4 a = p[o*2], b = p[o*2+1];
            uint32_t bits = nz4(a.x) | (nz4(a.y) << 4) | (nz4(a.z) << 8) | (nz4(a.w) << 12)
                          | (nz4(b.x) << 16) | (nz4(b.y) << 20)
                          | (nz4(b.z) << 24) | (nz4(b.w) << 28);
            g_mbits[gt * 4 + o] = bits;
        }
    } else {
        // int32/float32: thread packs 32 words -> 1 output word (bitwise nz)
        const uint4* p = (const uint4*)m + gt * 8;
        uint32_t bits = 0;
        #pragma unroll
        for (int i = 0; i < 8; i++) {
            uint4 v = p[i];
            bits |= (uint32_t)(v.x != 0u) << (i*4)
                  | (uint32_t)(v.y != 0u) << (i*4+1)
                  | (uint32_t)(v.z != 0u) << (i*4+2)
                  | (uint32_t)(v.w != 0u) << (i*4+3);
        }
        g_mbits[gt] = bits;
    }
}

// ======================== pipelined tensor-core GEMM ========================
#define CH 5120
#define GEMM_SMEM (8 * CH * 2)

__global__ __launch_bounds__(256, 2) void gemm_mma_kernel(
    const float* __restrict__ q, const float* __restrict__ h,
    float* __restrict__ out, int mode_base)
{
    extern __shared__ __align__(16) __half dsm[];
    __half* sAhi = dsm;            // [2][CH]
    __half* sAlo = dsm + 2*CH;
    __half* sWhi = dsm + 4*CH;
    __half* sWlo = dsm + 6*CH;

    int mode = mode_base + blockIdx.y;
    const float* A = (mode == 0) ? q : h;

    int tid = threadIdx.x, wid = tid >> 5, lane = tid & 31;
    int row0 = blockIdx.x * 128;
    int wr = wid & 1, wc = wid >> 1;
    int mi = lane >> 3, ri = lane & 7;

    float c[4][4][4] = {};

    uint32_t a_lo = (uint32_t)(((lane & 15) * 40 + (lane >> 4) * 8) * 2);
    uint32_t b_lo = (uint32_t)((((mi >> 1) * 8 + ri) * 40 + (mi & 1) * 8) * 2);
    uint32_t sAhi_b = smem_u32(sAhi), sAlo_b = smem_u32(sAlo);
    uint32_t sWhi_b = smem_u32(sWhi), sWlo_b = smem_u32(sWlo);

    int r_st = tid >> 1, kh_st = (tid & 1) * 16;
    uint32_t st_d = (uint32_t)((r_st * 40 + kh_st) * 2);
    const __half* Whi = g_Whi + mode * 16384;
    const __half* Wlo = g_Wlo + mode * 16384;

    // prologue: chunk 0
    {
        const __half* ws = Whi + r_st * 128 + kh_st;
        const __half* wl = Wlo + r_st * 128 + kh_st;
        CP_ASYNC16(sWhi_b + st_d,      ws);
        CP_ASYNC16(sWhi_b + st_d + 16, ws + 8);
        CP_ASYNC16(sWlo_b + st_d,      wl);
        CP_ASYNC16(sWlo_b + st_d + 16, wl + 8);
        if (mode == 3) {
            const __half* as = g_HPhi + (size_t)(row0 + r_st) * ED + kh_st;
            const __half* al = g_HPlo + (size_t)(row0 + r_st) * ED + kh_st;
            CP_ASYNC16(sAhi_b + st_d,      as);
            CP_ASYNC16(sAhi_b + st_d + 16, as + 8);
            CP_ASYNC16(sAlo_b + st_d,      al);
            CP_ASYNC16(sAlo_b + st_d + 16, al + 8);
        } else {
            const float* ap = A + (size_t)(row0 + r_st) * ED + kh_st;
            #pragma unroll
            for (int j4 = 0; j4 < 4; j4++) {
                float4 v = *(const float4*)(ap + j4 * 4);
                float vv[4] = {v.x, v.y, v.z, v.w};
                __half hi[4], lo[4];
                #pragma unroll
                for (int u = 0; u < 4; u++) {
                    hi[u] = __float2half_rn(vv[u]);
                    lo[u] = __float2half_rn(vv[u] - __half2float(hi[u]));
                }
                *(uint2*)(sAhi + r_st*40 + kh_st + j4*4) = *(uint2*)hi;
                *(uint2*)(sAlo + r_st*40 + kh_st + j4*4) = *(uint2*)lo;
            }
        }
        CP_COMMIT();
    }

    for (int kc = 0; kc < 4; kc++) {
        CP_WAIT0();
        __syncthreads();
        int p = kc & 1;
        uint32_t off_p = (uint32_t)(p * CH * 2);

        float4 rA[4];
        if (kc < 3) {
            int pn = p ^ 1;
            uint32_t off_n = (uint32_t)(pn * CH * 2);
            const __half* ws = Whi + r_st * 128 + (kc+1)*32 + kh_st;
            const __half* wl = Wlo + r_st * 128 + (kc+1)*32 + kh_st;
            CP_ASYNC16(sWhi_b + off_n + st_d,      ws);
            CP_ASYNC16(sWhi_b + off_n + st_d + 16, ws + 8);
            CP_ASYNC16(sWlo_b + off_n + st_d,      wl);
            CP_ASYNC16(sWlo_b + off_n + st_d + 16, wl + 8);
            if (mode == 3) {
                const __half* as = g_HPhi + (size_t)(row0 + r_st) * ED + (kc+1)*32 + kh_st;
                const __half* al = g_HPlo + (size_t)(row0 + r_st) * ED + (kc+1)*32 + kh_st;
                CP_ASYNC16(sAhi_b + off_n + st_d,      as);
                CP_ASYNC16(sAhi_b + off_n + st_d + 16, as + 8);
                CP_ASYNC16(sAlo_b + off_n + st_d,      al);
                CP_ASYNC16(sAlo_b + off_n + st_d + 16, al + 8);
            } else {
                const float* ap = A + (size_t)(row0 + r_st) * ED + (kc+1)*32 + kh_st;
                #pragma unroll
                for (int j4 = 0; j4 < 4; j4++) rA[j4] = *(const float4*)(ap + j4 * 4);
            }
            CP_COMMIT();
        }

        #pragma unroll
        for (int ks = 0; ks < 2; ks++) {
            uint32_t koff = (uint32_t)(ks * 32);
            uint32_t bhi[2][4], blo[2][4];
            #pragma unroll
            for (int nb = 0; nb < 2; nb++) {
                uint32_t no = (uint32_t)((wc*32 + nb*16) * 80) + koff + b_lo + off_p;
                LDSM_X4(bhi[nb][0], bhi[nb][1], bhi[nb][2], bhi[nb][3], sWhi_b + no);
                LDSM_X4(blo[nb][0], blo[nb][1], blo[nb][2], blo[nb][3], sWlo_b + no);
            }
            #pragma unroll
            for (int mb = 0; mb < 4; mb++) {
                uint32_t ro = (uint32_t)((wr*64 + mb*16) * 80) + koff + a_lo + off_p;
                uint32_t ahi[4], alo[4];
                LDSM_X4(ahi[0], ahi[1], ahi[2], ahi[3], sAhi_b + ro);
                LDSM_X4(alo[0], alo[1], alo[2], alo[3], sAlo_b + ro);
                #pragma unroll
                for (int ns = 0; ns < 4; ns++) {
                    const uint32_t* bh = &bhi[ns >> 1][(ns & 1) * 2];
                    const uint32_t* bl = &blo[ns >> 1][(ns & 1) * 2];
                    mma_k16(c[mb][ns], ahi, bh);
                    mma_k16(c[mb][ns], alo, bh);
                    mma_k16(c[mb][ns], ahi, bl);
                }
            }
        }

        if (kc < 3 && mode < 3) {
            int pn = p ^ 1;
            #pragma unroll
            for (int j4 = 0; j4 < 4; j4++) {
                float vv[4] = {rA[j4].x, rA[j4].y, rA[j4].z, rA[j4].w};
                __half hi[4], lo[4];
                #pragma unroll
                for (int u = 0; u < 4; u++) {
                    hi[u] = __float2half_rn(vv[u]);
                    lo[u] = __float2half_rn(vv[u] - __half2float(hi[u]));
                }
                *(uint2*)(sAhi + pn*CH + r_st*40 + kh_st + j4*4) = *(uint2*)hi;
                *(uint2*)(sAlo + pn*CH + r_st*40 + kh_st + j4*4) = *(uint2*)lo;
            }
        }
    }

    // epilogue
    int g = lane >> 2, t = lane & 3;
    #pragma unroll
    for (int mb = 0; mb < 4; mb++) {
        int grow = row0 + wr*64 + mb*16 + g;
        #pragma unroll
        for (int ns = 0; ns < 4; ns++) {
            int col = wc*32 + ns*8 + 2*t;
            float* cc = c[mb][ns];
            if (mode == 3) {
                *(float2*)(out + (size_t)grow * ED + col) = make_float2(cc[0], cc[1]);
                *(float2*)(out + (size_t)(grow + 8) * ED + col) = make_float2(cc[2], cc[3]);
            } else {
                int head = col >> 4, e = col & 15;
                int b = grow >> 10, n = grow & 1023;
                if (mode == 2) {
                    __half* vt = g_Vt + ((size_t)(b*NH + head) * 16 + e) * 1024;
                    vt[n]            = __float2half_rn(cc[0]);
                    vt[1024 + n]     = __float2half_rn(cc[1]);
                    vt[n + 8]        = __float2half_rn(cc[2]);
                    vt[1024 + n + 8] = __float2half_rn(cc[3]);
                } else {
                    __half* HI = (mode == 0) ? g_Qhi : g_Khi;
                    size_t base0 = ((size_t)(b*NH + head) * 1024 + n) * 16 + e;
                    size_t base1 = base0 + 8 * 16;
                    __half h0 = __float2half_rn(cc[0]), h1 = __float2half_rn(cc[1]);
                    __half h2 = __float2half_rn(cc[2]), h3 = __float2half_rn(cc[3]);
                    *(uint32_t*)(HI + base0) = packh2_u(h0, h1);
                    *(uint32_t*)(HI + base1) = packh2_u(h2, h3);
                    if (mode == 0) {
                        *(uint32_t*)(g_Qlo + base0) =
                            packf2(cc[0] - __half2float(h0), cc[1] - __half2float(h1));
                        *(uint32_t*)(g_Qlo + base1) =
                            packf2(cc[2] - __half2float(h2), cc[3] - __half2float(h3));
                    }
                }
            }
        }
    }
}

// ======================== flash attention (running max, R10 numerics) ========
__device__ __forceinline__ void store_hl(__half* HI, __half* LO, size_t off,
                                         float x, float y) {
    __half hx = __float2half_rn(x), hy = __float2half_rn(y);
    *(uint32_t*)(HI + off) = packh2_u(hx, hy);
    *(uint32_t*)(LO + off) = packf2(x - __half2float(hx), y - __half2float(hy));
}

__global__ __launch_bounds__(256, 2) void attn_mma_kernel(
    const __half* __restrict__ Qhi, const __half* __restrict__ Qlo,
    const __half* __restrict__ Khig, const __half* __restrict__ Vtg,
    const uint32_t* __restrict__ Mbits)
{
    __shared__ __align__(16) __half sKhi[2][128*24];
    __shared__ __align__(16) __half sVt [2][16*136];

    int tid = threadIdx.x, wid = tid >> 5, lane = tid & 31;
    int g = lane >> 2, t = lane & 3;
    int hd = blockIdx.x, q0 = blockIdx.y * 128, b = blockIdx.z;

    const __half* Kh = Khig + (size_t)(b*NH+hd) * GSZ * HD;
    const __half* Vg = Vtg  + (size_t)(b*NH+hd) * HD * GSZ;

    int k_row = tid >> 1, k_half = tid & 1;
    int v_e = tid >> 4, v_seg = tid & 15;
    uint32_t dKhi[2], dVt[2];
    #pragma unroll
    for (int bb = 0; bb < 2; bb++) {
        dKhi[bb] = smem_u32(&sKhi[bb][0]) + k_row * 48 + k_half * 16;
        dVt[bb]  = smem_u32(&sVt[bb][0])  + v_e * 272 + v_seg * 16;
    }

    int mi = lane >> 3, ri = lane & 7;
    uint32_t k_lb = (uint32_t)((((mi >> 1) * 8 + ri) * 24 + (mi & 1) * 8) * 2);
    uint32_t v_lb = (uint32_t)((((mi & 1) * 8 + ri) * 136 + (mi >> 1) * 8) * 2);

    {
        const __half* s1 = Kh + (size_t)k_row * 16 + k_half * 8;
        const __half* s3 = Vg + (size_t)v_e * GSZ + v_seg * 8;
        CP_ASYNC16(dKhi[0], s1); CP_ASYNC16(dVt[0], s3);
        CP_COMMIT();
    }

    uint32_t qhi[4], qlo[4];
    {
        size_t qb = ((size_t)(b*NH+hd) * NQ + q0 + wid*16) * 16;
        #pragma unroll
        for (int i = 0; i < 4; i++) {
            int r = g + (i & 1) * 8;
            int cix = 2*t + (i >> 1) * 8;
            qhi[i] = *(const uint32_t*)(Qhi + qb + r*16 + cix);
            qlo[i] = *(const uint32_t*)(Qlo + qb + r*16 + cix);
        }
    }

    int rg0 = q0 + wid*16 + g;
    const uint32_t* mb0p = Mbits + ((size_t)b * NQ + rg0) * 32;
    const uint32_t* mb1p = mb0p + 8 * 32;

    const uint32_t ones2[2] = {0x3C003C00u, 0x3C003C00u};
    float o[8] = {};
    float lacc[4] = {};
    float m0 = -1e30f, m1 = -1e30f;

    for (int t8 = 0; t8 < 8; t8++) {
        CP_WAIT0();
        __syncthreads();   // single barrier per tile: orders prior reads before prefetch
        int bb = t8 & 1;

        if (t8 < 7) {
            int k0n = (t8 + 1) * 128;
            const __half* s1 = Kh + (size_t)(k0n + k_row) * 16 + k_half * 8;
            const __half* s3 = Vg + (size_t)v_e * GSZ + k0n + v_seg * 8;
            CP_ASYNC16(dKhi[bb ^ 1], s1); CP_ASYNC16(dVt[bb ^ 1], s3);
            CP_COMMIT();
        }

        uint4 mw0 = *(const uint4*)(mb0p + t8 * 4);
        uint4 mw1 = *(const uint4*)(mb1p + t8 * 4);

        uint32_t khb = smem_u32(&sKhi[bb][0]) + k_lb;
        uint32_t vtb = smem_u32(&sVt[bb][0]) + v_lb;

        #pragma unroll
        for (int hf = 0; hf < 2; hf++) {
            float s[8][4];
            #pragma unroll
            for (int kc = 0; kc < 8; kc++)
                s[kc][0] = s[kc][1] = s[kc][2] = s[kc][3] = 0.f;
            #pragma unroll
            for (int j = 0; j < 4; j++) {
                uint32_t kh[4];
                uint32_t off = (uint32_t)((hf*64 + j*16) * 48);
                LDSM_X4(kh[0], kh[1], kh[2], kh[3], khb + off);
                mma_k16(s[2*j],   qhi, kh);
                mma_k16(s[2*j],   qlo, kh);
                mma_k16(s[2*j+1], qhi, kh+2);
                mma_k16(s[2*j+1], qlo, kh+2);
            }
            // row max over RAW scores (valid upper bound for softmax shift)
            float tm0 = -1e30f, tm1 = -1e30f;
            #pragma unroll
            for (int kc = 0; kc < 8; kc++) {
                tm0 = fmaxf(tm0, fmaxf(s[kc][0], s[kc][1]));
                tm1 = fmaxf(tm1, fmaxf(s[kc][2], s[kc][3]));
            }
            tm0 = fmaxf(tm0, __shfl_xor_sync(0xffffffffu, tm0, 1));
            tm0 = fmaxf(tm0, __shfl_xor_sync(0xffffffffu, tm0, 2));
            tm1 = fmaxf(tm1, __shfl_xor_sync(0xffffffffu, tm1, 1));
            tm1 = fmaxf(tm1, __shfl_xor_sync(0xffffffffu, tm1, 2));

            float mn0 = fmaxf(m0, tm0);
            float mn1 = fmaxf(m1, tm1);
            float f0 = ex2f(m0 - mn0), f1 = ex2f(m1 - mn1);
            m0 = mn0; m1 = mn1;
            o[0] *= f0; o[1] *= f0; o[4] *= f0; o[5] *= f0;
            o[2] *= f1; o[3] *= f1; o[6] *= f1; o[7] *= f1;
            lacc[0] *= f0; lacc[2] *= f1;

            uint32_t w0a = hf ? mw0.z : mw0.x, w0b = hf ? mw0.w : mw0.y;
            uint32_t w1a = hf ? mw1.z : mw1.x, w1b = hf ? mw1.w : mw1.y;

            #pragma unroll
            for (int jj = 0; jj < 4; jj++) {
                uint32_t v0e, v1e, v0o, v1o;
                LDSM_X4(v0e, v1e, v0o, v1o, vtb + (uint32_t)((hf*64 + jj*16) * 2));
                uint32_t a[4];
                #pragma unroll
                for (int q2 = 0; q2 < 2; q2++) {
                    int kc = 2*jj + q2;
                    uint32_t wa = (kc < 4) ? w0a : w0b;
                    uint32_t wb = (kc < 4) ? w1a : w1b;
                    int sh = (kc & 3) * 8 + 2*t;
                    uint32_t p0 = (wa >> sh) & 3u;
                    uint32_t p1 = (wb >> sh) & 3u;
                    uint32_t km0 = ((p0 & 1) ? 0u : 0xFFFFu) | ((p0 & 2) ? 0u : 0xFFFF0000u);
                    uint32_t km1 = ((p1 & 1) ? 0u : 0xFFFFu) | ((p1 & 2) ? 0u : 0xFFFF0000u);
                    __half2 d01 = __floats2half2_rn(s[kc][0] - mn0, s[kc][1] - mn0);
                    __half2 d23 = __floats2half2_rn(s[kc][2] - mn1, s[kc][3] - mn1);
                    a[2*q2]     = h2u(h2exp2(d01)) & km0;
                    a[2*q2 + 1] = h2u(h2exp2(d23)) & km1;
                }
                uint32_t be[2] = {v0e, v0o};
                uint32_t bo[2] = {v1e, v1o};
                mma_k16(o,     a, be);
                mma_k16(o + 4, a, bo);
                mma_k16(lacc,  a, ones2);
            }
        }
        // (no end-of-loop barrier: the top barrier next iteration suffices)
    }

    float inv0 = 1.f / lacc[0], inv1 = 1.f / lacc[2];

    size_t r0 = ((size_t)b*NQ + q0 + wid*16 + g) * ED + hd * HD;
    size_t r1 = r0 + 8 * ED;
    store_hl(g_HPhi, g_HPlo, r0 + 2*t,     o[0]*inv0, o[1]*inv0);
    store_hl(g_HPhi, g_HPlo, r0 + 8 + 2*t, o[4]*inv0, o[5]*inv0);
    store_hl(g_HPhi, g_HPlo, r1 + 2*t,     o[2]*inv1, o[3]*inv1);
    store_hl(g_HPhi, g_HPlo, r1 + 8 + 2*t, o[6]*inv1, o[7]*inv1);
}

// ======================== launch ========================
extern "C" void kernel_launch(void* const* d_in, const int* in_sizes, int n_in,
                              void* d_out, int out_size)
{
    const float* q = (const float*)d_in[0];
    const float* h = (const float*)d_in[1];
    const void*  mask_raw = d_in[2];
    const float* Wq = (const float*)d_in[3];
    const float* Wk = (const float*)d_in[4];
    const float* Wv = (const float*)d_in[5];
    const float* Wout = (const float*)d_in[6];
    float* out = (float*)d_out;

    __half *Qhi, *Qlo, *Khi, *Vt;
    uint32_t* MB;
    cudaGetSymbolAddress((void**)&Qhi, g_Qhi);
    cudaGetSymbolAddress((void**)&Qlo, g_Qlo);
    cudaGetSymbolAddress((void**)&Khi, g_Khi);
    cudaGetSymbolAddress((void**)&Vt,  g_Vt);
    cudaGetSymbolAddress((void**)&MB,  g_mbits);

    cudaFuncSetAttribute(gemm_mma_kernel,
                         cudaFuncAttributeMaxDynamicSharedMemorySize, GEMM_SMEM);

    // W split (y=0..3) + mask dtype detect (y=4, one block)
    split_w_kernel<<<dim3(64, 5), 256>>>(Wq, Wk, Wv, Wout,
                                         (const unsigned int*)mask_raw);
    // bitpack (grid sized for the 1-word-per-thread path; u8 path early-outs)
    bitpack_mask_kernel<<<(BB*NQ*32) / 256, 256>>>(mask_raw);

    gemm_mma_kernel<<<dim3(MROWS / 128, 3), 256, GEMM_SMEM>>>(q, h, out, 0);

    dim3 grid(NH, NQ / 128, BB);
    attn_mma_kernel<<<grid, 256>>>(Qhi, Qlo, Khi, Vt, MB);

    gemm_mma_kernel<<<dim3(MROWS / 128, 1), 256, GEMM_SMEM>>>(q, h, out, 3);
}

// round 15
// speedup vs baseline: 1.1346x; 1.0635x over previous
#include <cuda_runtime.h>
#include <cuda_fp16.h>
#include <stdint.h>

#define BB 32
#define NQ 1024
#define GSZ 1024
#define ED 128
#define NH 8
#define HD 16
#define MROWS (BB*NQ)

__device__ __half g_Qhi[(size_t)BB*NH*NQ*HD];
__device__ __half g_Qlo[(size_t)BB*NH*NQ*HD];
__device__ __half g_Khi[(size_t)BB*NH*GSZ*HD];
__device__ __half g_Vt [(size_t)BB*NH*HD*GSZ];   // [b,h,e,g]
__device__ __half g_HPhi[(size_t)MROWS*ED];
__device__ __half g_HPlo[(size_t)MROWS*ED];
__device__ __half g_Whi[4*128*128];              // [mode][n][k]
__device__ __half g_Wlo[4*128*128];
__device__ uint32_t g_mbits[(size_t)BB*NQ*32];
__device__ int g_mdtype;

// ======================== helpers ========================
__device__ __forceinline__ float ex2f(float x) {
    float r; asm("ex2.approx.f32 %0, %1;" : "=f"(r) : "f"(x));
    return r;
}
__device__ __forceinline__ uint32_t packh2_u(__half a, __half b) {
    __half2 h; h.x = a; h.y = b;
    return *(uint32_t*)&h;
}
__device__ __forceinline__ uint32_t packf2(float a, float b) {
    __half2 h = __floats2half2_rn(a, b);
    return *(uint32_t*)&h;
}
__device__ __forceinline__ uint32_t h2u(__half2 h) { return *(uint32_t*)&h; }
__device__ __forceinline__ uint32_t smem_u32(const void* p) {
    uint32_t a;
    asm("{ .reg .u64 t; cvta.to.shared.u64 t, %1; cvt.u32.u64 %0, t; }" : "=r"(a) : "l"(p));
    return a;
}
__device__ __forceinline__ void mma_k16(float* c, const uint32_t* a, const uint32_t* b) {
    asm volatile("mma.sync.aligned.m16n8k16.row.col.f32.f16.f16.f32 "
        "{%0,%1,%2,%3}, {%4,%5,%6,%7}, {%8,%9}, {%0,%1,%2,%3};"
        : "+f"(c[0]), "+f"(c[1]), "+f"(c[2]), "+f"(c[3])
        : "r"(a[0]), "r"(a[1]), "r"(a[2]), "r"(a[3]), "r"(b[0]), "r"(b[1]));
}
#define LDSM_X4(r0, r1, r2, r3, addr) \
    asm volatile("ldmatrix.sync.aligned.m8n8.x4.shared.b16 {%0,%1,%2,%3}, [%4];" \
        : "=r"(r0), "=r"(r1), "=r"(r2), "=r"(r3) : "r"(addr))
#define CP_ASYNC16(dst, src) \
    asm volatile("cp.async.cg.shared.global [%0], [%1], 16;" :: "r"(dst), "l"(src))
#define CP_COMMIT() asm volatile("cp.async.commit_group;" ::: "memory")
#define CP_WAIT0()  asm volatile("cp.async.wait_group 0;" ::: "memory")

// mask bit -> float init: 0.0f (clear) or -3.4e38f (set), 3 ALU ops
__device__ __forceinline__ float mask_init(uint32_t w, int sl) {
    return __uint_as_float(((uint32_t)((int)(w << sl) >> 31)) & 0xFF7FFFFFu);
}

// nonzero-byte -> 4-bit nibble
__device__ __forceinline__ uint32_t nz4(uint32_t w) {
    uint32_t nz = (((w & 0x7F7F7F7Fu) + 0x7F7F7F7Fu) | w) & 0x80808080u;
    return (((nz >> 7) * 0x01020408u) >> 24) & 0xFu;
}

// ======================== W pre-split (+ mask dtype detect slice) ========
__global__ __launch_bounds__(256) void split_w_kernel(
    const float* __restrict__ Wq, const float* __restrict__ Wk,
    const float* __restrict__ Wv, const float* __restrict__ Wout,
    const unsigned int* __restrict__ mask_raw)
{
    int mode = blockIdx.y;
    if (mode == 4) {
        if (blockIdx.x != 0) return;
        __shared__ int sf32, sgt1;
        if (threadIdx.x == 0) { sf32 = 0; sgt1 = 0; }
        __syncthreads();
        for (int i = threadIdx.x; i < 2048; i += blockDim.x) {
            unsigned int w = mask_raw[i];
            if (w == 0x3F800000u) sf32 = 1;
            else if (w > 1u) sgt1 = 1;
        }
        __syncthreads();
        if (threadIdx.x == 0) g_mdtype = sf32 ? 2 : (sgt1 ? 0 : 1);
        return;
    }
    const float* W = (mode == 0) ? Wq : (mode == 1 ? Wk : (mode == 2 ? Wv : Wout));
    int idx = blockIdx.x * 256 + threadIdx.x;
    int n = idx >> 7, k = idx & 127;
    float w = (mode < 3)
        ? W[(size_t)(n >> 4) * (ED * HD) + (size_t)k * HD + (n & 15)]
        : W[(size_t)k * ED + n];
    if (mode == 0) w *= 0.36067376022224085f;   // 0.25 * log2(e)
    __half hh = __float2half_rn(w);
    g_Whi[mode * 16384 + idx] = hh;
    g_Wlo[mode * 16384 + idx] = __float2half_rn(w - __half2float(hh));
}

// ======================== mask bitpack (vectorized) ========================
__global__ __launch_bounds__(256) void bitpack_mask_kernel(const void* __restrict__ m)
{
    int dt = g_mdtype;
    size_t gt = (size_t)blockIdx.x * 256 + threadIdx.x;
    if (dt == 0) {
        if (gt >= (size_t)BB*NQ*32 / 4) return;
        const uint4* p = (const uint4*)m + gt * 8;
        #pragma unroll
        for (int o = 0; o < 4; o++) {
            uint4 a = p[o*2], b = p[o*2+1];
            uint32_t bits = nz4(a.x) | (nz4(a.y) << 4) | (nz4(a.z) << 8) | (nz4(a.w) << 12)
                          | (nz4(b.x) << 16) | (nz4(b.y) << 20)
                          | (nz4(b.z) << 24) | (nz4(b.w) << 28);
            g_mbits[gt * 4 + o] = bits;
        }
    } else {
        const uint4* p = (const uint4*)m + gt * 8;
        uint32_t bits = 0;
        #pragma unroll
        for (int i = 0; i < 8; i++) {
            uint4 v = p[i];
            bits |= (uint32_t)(v.x != 0u) << (i*4)
                  | (uint32_t)(v.y != 0u) << (i*4+1)
                  | (uint32_t)(v.z != 0u) << (i*4+2)
                  | (uint32_t)(v.w != 0u) << (i*4+3);
        }
        g_mbits[gt] = bits;
    }
}

// ======================== pipelined tensor-core GEMM ========================
#define CH 5120
#define GEMM_SMEM (8 * CH * 2)

__global__ __launch_bounds__(256, 2) void gemm_mma_kernel(
    const float* __restrict__ q, const float* __restrict__ h,
    float* __restrict__ out, int mode_base)
{
    extern __shared__ __align__(16) __half dsm[];
    __half* sAhi = dsm;            // [2][CH]
    __half* sAlo = dsm + 2*CH;
    __half* sWhi = dsm + 4*CH;
    __half* sWlo = dsm + 6*CH;

    int mode = mode_base + blockIdx.y;
    const float* A = (mode == 0) ? q : h;

    int tid = threadIdx.x, wid = tid >> 5, lane = tid & 31;
    int row0 = blockIdx.x * 128;
    int wr = wid & 1, wc = wid >> 1;
    int mi = lane >> 3, ri = lane & 7;

    float c[4][4][4] = {};

    uint32_t a_lo = (uint32_t)(((lane & 15) * 40 + (lane >> 4) * 8) * 2);
    uint32_t b_lo = (uint32_t)((((mi >> 1) * 8 + ri) * 40 + (mi & 1) * 8) * 2);
    uint32_t sAhi_b = smem_u32(sAhi), sAlo_b = smem_u32(sAlo);
    uint32_t sWhi_b = smem_u32(sWhi), sWlo_b = smem_u32(sWlo);

    int r_st = tid >> 1, kh_st = (tid & 1) * 16;
    uint32_t st_d = (uint32_t)((r_st * 40 + kh_st) * 2);
    const __half* Whi = g_Whi + mode * 16384;
    const __half* Wlo = g_Wlo + mode * 16384;

    // prologue: chunk 0
    {
        const __half* ws = Whi + r_st * 128 + kh_st;
        const __half* wl = Wlo + r_st * 128 + kh_st;
        CP_ASYNC16(sWhi_b + st_d,      ws);
        CP_ASYNC16(sWhi_b + st_d + 16, ws + 8);
        CP_ASYNC16(sWlo_b + st_d,      wl);
        CP_ASYNC16(sWlo_b + st_d + 16, wl + 8);
        if (mode == 3) {
            const __half* as = g_HPhi + (size_t)(row0 + r_st) * ED + kh_st;
            const __half* al = g_HPlo + (size_t)(row0 + r_st) * ED + kh_st;
            CP_ASYNC16(sAhi_b + st_d,      as);
            CP_ASYNC16(sAhi_b + st_d + 16, as + 8);
            CP_ASYNC16(sAlo_b + st_d,      al);
            CP_ASYNC16(sAlo_b + st_d + 16, al + 8);
        } else {
            const float* ap = A + (size_t)(row0 + r_st) * ED + kh_st;
            #pragma unroll
            for (int j4 = 0; j4 < 4; j4++) {
                float4 v = *(const float4*)(ap + j4 * 4);
                float vv[4] = {v.x, v.y, v.z, v.w};
                __half hi[4], lo[4];
                #pragma unroll
                for (int u = 0; u < 4; u++) {
                    hi[u] = __float2half_rn(vv[u]);
                    lo[u] = __float2half_rn(vv[u] - __half2float(hi[u]));
                }
                *(uint2*)(sAhi + r_st*40 + kh_st + j4*4) = *(uint2*)hi;
                *(uint2*)(sAlo + r_st*40 + kh_st + j4*4) = *(uint2*)lo;
            }
        }
        CP_COMMIT();
    }

    for (int kc = 0; kc < 4; kc++) {
        CP_WAIT0();
        __syncthreads();
        int p = kc & 1;
        uint32_t off_p = (uint32_t)(p * CH * 2);

        float4 rA[4];
        if (kc < 3) {
            int pn = p ^ 1;
            uint32_t off_n = (uint32_t)(pn * CH * 2);
            const __half* ws = Whi + r_st * 128 + (kc+1)*32 + kh_st;
            const __half* wl = Wlo + r_st * 128 + (kc+1)*32 + kh_st;
            CP_ASYNC16(sWhi_b + off_n + st_d,      ws);
            CP_ASYNC16(sWhi_b + off_n + st_d + 16, ws + 8);
            CP_ASYNC16(sWlo_b + off_n + st_d,      wl);
            CP_ASYNC16(sWlo_b + off_n + st_d + 16, wl + 8);
            if (mode == 3) {
                const __half* as = g_HPhi + (size_t)(row0 + r_st) * ED + (kc+1)*32 + kh_st;
                const __half* al = g_HPlo + (size_t)(row0 + r_st) * ED + (kc+1)*32 + kh_st;
                CP_ASYNC16(sAhi_b + off_n + st_d,      as);
                CP_ASYNC16(sAhi_b + off_n + st_d + 16, as + 8);
                CP_ASYNC16(sAlo_b + off_n + st_d,      al);
                CP_ASYNC16(sAlo_b + off_n + st_d + 16, al + 8);
            } else {
                const float* ap = A + (size_t)(row0 + r_st) * ED + (kc+1)*32 + kh_st;
                #pragma unroll
                for (int j4 = 0; j4 < 4; j4++) rA[j4] = *(const float4*)(ap + j4 * 4);
            }
            CP_COMMIT();
        }

        #pragma unroll
        for (int ks = 0; ks < 2; ks++) {
            uint32_t koff = (uint32_t)(ks * 32);
            uint32_t bhi[2][4], blo[2][4];
            #pragma unroll
            for (int nb = 0; nb < 2; nb++) {
                uint32_t no = (uint32_t)((wc*32 + nb*16) * 80) + koff + b_lo + off_p;
                LDSM_X4(bhi[nb][0], bhi[nb][1], bhi[nb][2], bhi[nb][3], sWhi_b + no);
                LDSM_X4(blo[nb][0], blo[nb][1], blo[nb][2], blo[nb][3], sWlo_b + no);
            }
            #pragma unroll
            for (int mb = 0; mb < 4; mb++) {
                uint32_t ro = (uint32_t)((wr*64 + mb*16) * 80) + koff + a_lo + off_p;
                uint32_t ahi[4], alo[4];
                LDSM_X4(ahi[0], ahi[1], ahi[2], ahi[3], sAhi_b + ro);
                LDSM_X4(alo[0], alo[1], alo[2], alo[3], sAlo_b + ro);
                #pragma unroll
                for (int ns = 0; ns < 4; ns++) {
                    const uint32_t* bh = &bhi[ns >> 1][(ns & 1) * 2];
                    const uint32_t* bl = &blo[ns >> 1][(ns & 1) * 2];
                    mma_k16(c[mb][ns], ahi, bh);
                    mma_k16(c[mb][ns], alo, bh);
                    mma_k16(c[mb][ns], ahi, bl);
                }
            }
        }

        if (kc < 3 && mode < 3) {
            int pn = p ^ 1;
            #pragma unroll
            for (int j4 = 0; j4 < 4; j4++) {
                float vv[4] = {rA[j4].x, rA[j4].y, rA[j4].z, rA[j4].w};
                __half hi[4], lo[4];
                #pragma unroll
                for (int u = 0; u < 4; u++) {
                    hi[u] = __float2half_rn(vv[u]);
                    lo[u] = __float2half_rn(vv[u] - __half2float(hi[u]));
                }
                *(uint2*)(sAhi + pn*CH + r_st*40 + kh_st + j4*4) = *(uint2*)hi;
                *(uint2*)(sAlo + pn*CH + r_st*40 + kh_st + j4*4) = *(uint2*)lo;
            }
        }
    }

    // epilogue
    int g = lane >> 2, t = lane & 3;
    #pragma unroll
    for (int mb = 0; mb < 4; mb++) {
        int grow = row0 + wr*64 + mb*16 + g;
        #pragma unroll
        for (int ns = 0; ns < 4; ns++) {
            int col = wc*32 + ns*8 + 2*t;
            float* cc = c[mb][ns];
            if (mode == 3) {
                *(float2*)(out + (size_t)grow * ED + col) = make_float2(cc[0], cc[1]);
                *(float2*)(out + (size_t)(grow + 8) * ED + col) = make_float2(cc[2], cc[3]);
            } else {
                int head = col >> 4, e = col & 15;
                int b = grow >> 10, n = grow & 1023;
                if (mode == 2) {
                    __half* vt = g_Vt + ((size_t)(b*NH + head) * 16 + e) * 1024;
                    vt[n]            = __float2half_rn(cc[0]);
                    vt[1024 + n]     = __float2half_rn(cc[1]);
                    vt[n + 8]        = __float2half_rn(cc[2]);
                    vt[1024 + n + 8] = __float2half_rn(cc[3]);
                } else {
                    __half* HI = (mode == 0) ? g_Qhi : g_Khi;
                    size_t base0 = ((size_t)(b*NH + head) * 1024 + n) * 16 + e;
                    size_t base1 = base0 + 8 * 16;
                    __half h0 = __float2half_rn(cc[0]), h1 = __float2half_rn(cc[1]);
                    __half h2 = __float2half_rn(cc[2]), h3 = __float2half_rn(cc[3]);
                    *(uint32_t*)(HI + base0) = packh2_u(h0, h1);
                    *(uint32_t*)(HI + base1) = packh2_u(h2, h3);
                    if (mode == 0) {
                        *(uint32_t*)(g_Qlo + base0) =
                            packf2(cc[0] - __half2float(h0), cc[1] - __half2float(h1));
                        *(uint32_t*)(g_Qlo + base1) =
                            packf2(cc[2] - __half2float(h2), cc[3] - __half2float(h3));
                    }
                }
            }
        }
    }
}

// ======================== flash attention (mask folded into acc init) ========
__device__ __forceinline__ void store_hl(__half* HI, __half* LO, size_t off,
                                         float x, float y) {
    __half hx = __float2half_rn(x), hy = __float2half_rn(y);
    *(uint32_t*)(HI + off) = packh2_u(hx, hy);
    *(uint32_t*)(LO + off) = packf2(x - __half2float(hx), y - __half2float(hy));
}

__global__ __launch_bounds__(256, 2) void attn_mma_kernel(
    const __half* __restrict__ Qhi, const __half* __restrict__ Qlo,
    const __half* __restrict__ Khig, const __half* __restrict__ Vtg,
    const uint32_t* __restrict__ Mbits)
{
    __shared__ __align__(16) __half sKhi[2][128*24];
    __shared__ __align__(16) __half sVt [2][16*136];

    int tid = threadIdx.x, wid = tid >> 5, lane = tid & 31;
    int g = lane >> 2, t = lane & 3;
    int hd = blockIdx.x, q0 = blockIdx.y * 128, b = blockIdx.z;

    const __half* Kh = Khig + (size_t)(b*NH+hd) * GSZ * HD;
    const __half* Vg = Vtg  + (size_t)(b*NH+hd) * HD * GSZ;

    int k_row = tid >> 1, k_half = tid & 1;
    int v_e = tid >> 4, v_seg = tid & 15;
    uint32_t dKhi[2], dVt[2];
    #pragma unroll
    for (int bb = 0; bb < 2; bb++) {
        dKhi[bb] = smem_u32(&sKhi[bb][0]) + k_row * 48 + k_half * 16;
        dVt[bb]  = smem_u32(&sVt[bb][0])  + v_e * 272 + v_seg * 16;
    }

    int mi = lane >> 3, ri = lane & 7;
    uint32_t k_lb = (uint32_t)((((mi >> 1) * 8 + ri) * 24 + (mi & 1) * 8) * 2);
    uint32_t v_lb = (uint32_t)((((mi & 1) * 8 + ri) * 136 + (mi >> 1) * 8) * 2);

    {
        const __half* s1 = Kh + (size_t)k_row * 16 + k_half * 8;
        const __half* s3 = Vg + (size_t)v_e * GSZ + v_seg * 8;
        CP_ASYNC16(dKhi[0], s1); CP_ASYNC16(dVt[0], s3);
        CP_COMMIT();
    }

    uint32_t qhi[4], qlo[4];
    {
        size_t qb = ((size_t)(b*NH+hd) * NQ + q0 + wid*16) * 16;
        #pragma unroll
        for (int i = 0; i < 4; i++) {
            int r = g + (i & 1) * 8;
            int cix = 2*t + (i >> 1) * 8;
            qhi[i] = *(const uint32_t*)(Qhi + qb + r*16 + cix);
            qlo[i] = *(const uint32_t*)(Qlo + qb + r*16 + cix);
        }
    }

    int rg0 = q0 + wid*16 + g;
    const uint32_t* mb0p = Mbits + ((size_t)b * NQ + rg0) * 32;
    const uint32_t* mb1p = mb0p + 8 * 32;

    const uint32_t ones2[2] = {0x3C003C00u, 0x3C003C00u};
    float o[8] = {};
    float lacc[4] = {};
    float m0 = -1e30f, m1 = -1e30f;
    int t2 = 2 * t;

    for (int t8 = 0; t8 < 8; t8++) {
        CP_WAIT0();
        __syncthreads();
        int bb = t8 & 1;

        if (t8 < 7) {
            int k0n = (t8 + 1) * 128;
            const __half* s1 = Kh + (size_t)(k0n + k_row) * 16 + k_half * 8;
            const __half* s3 = Vg + (size_t)v_e * GSZ + k0n + v_seg * 8;
            CP_ASYNC16(dKhi[bb ^ 1], s1); CP_ASYNC16(dVt[bb ^ 1], s3);
            CP_COMMIT();
        }

        uint4 mw0 = *(const uint4*)(mb0p + t8 * 4);
        uint4 mw1 = *(const uint4*)(mb1p + t8 * 4);

        uint32_t khb = smem_u32(&sKhi[bb][0]) + k_lb;
        uint32_t vtb = smem_u32(&sVt[bb][0]) + v_lb;

        #pragma unroll
        for (int hf = 0; hf < 2; hf++) {
            uint32_t wa0 = hf ? mw0.z : mw0.x, wa1 = hf ? mw0.w : mw0.y;
            uint32_t wb0 = hf ? mw1.z : mw1.x, wb1 = hf ? mw1.w : mw1.y;

            // score accumulators initialized with mask bias:
            // 0.0 (unmasked) or -3.4e38 (masked) -> flows to -inf -> exp 0
            float s[8][4];
            #pragma unroll
            for (int kc = 0; kc < 8; kc++) {
                uint32_t wa = (kc < 4) ? wa0 : wa1;
                uint32_t wb = (kc < 4) ? wb0 : wb1;
                int sl = 31 - (kc & 3) * 8 - t2;
                s[kc][0] = mask_init(wa, sl);
                s[kc][1] = mask_init(wa, sl - 1);
                s[kc][2] = mask_init(wb, sl);
                s[kc][3] = mask_init(wb, sl - 1);
            }
            #pragma unroll
            for (int j = 0; j < 4; j++) {
                uint32_t kh[4];
                uint32_t off = (uint32_t)((hf*64 + j*16) * 48);
                LDSM_X4(kh[0], kh[1], kh[2], kh[3], khb + off);
                mma_k16(s[2*j],   qhi, kh);
                mma_k16(s[2*j],   qlo, kh);
                mma_k16(s[2*j+1], qhi, kh+2);
                mma_k16(s[2*j+1], qlo, kh+2);
            }
            // row max (masked elements are -3.4e38 -> excluded, matches reference)
            float tm0 = -1e30f, tm1 = -1e30f;
            #pragma unroll
            for (int kc = 0; kc < 8; kc++) {
                tm0 = fmaxf(tm0, fmaxf(s[kc][0], s[kc][1]));
                tm1 = fmaxf(tm1, fmaxf(s[kc][2], s[kc][3]));
            }
            tm0 = fmaxf(tm0, __shfl_xor_sync(0xffffffffu, tm0, 1));
            tm0 = fmaxf(tm0, __shfl_xor_sync(0xffffffffu, tm0, 2));
            tm1 = fmaxf(tm1, __shfl_xor_sync(0xffffffffu, tm1, 1));
            tm1 = fmaxf(tm1, __shfl_xor_sync(0xffffffffu, tm1, 2));

            float mn0 = fmaxf(m0, tm0);
            float mn1 = fmaxf(m1, tm1);
            float f0 = ex2f(m0 - mn0), f1 = ex2f(m1 - mn1);
            m0 = mn0; m1 = mn1;
            o[0] *= f0; o[1] *= f0; o[4] *= f0; o[5] *= f0;
            o[2] *= f1; o[3] *= f1; o[6] *= f1; o[7] *= f1;
            lacc[0] *= f0; lacc[2] *= f1;

            // exp + PV + l (no mask ops here: masked scores are -inf after cvt)
            #pragma unroll
            for (int jj = 0; jj < 4; jj++) {
                uint32_t v0e, v1e, v0o, v1o;
                LDSM_X4(v0e, v1e, v0o, v1o, vtb + (uint32_t)((hf*64 + jj*16) * 2));
                uint32_t a[4];
                #pragma unroll
                for (int q2 = 0; q2 < 2; q2++) {
                    int kc = 2*jj + q2;
                    __half2 d01 = __floats2half2_rn(s[kc][0] - mn0, s[kc][1] - mn0);
                    __half2 d23 = __floats2half2_rn(s[kc][2] - mn1, s[kc][3] - mn1);
                    a[2*q2]     = h2u(h2exp2(d01));
                    a[2*q2 + 1] = h2u(h2exp2(d23));
                }
                uint32_t be[2] = {v0e, v0o};
                uint32_t bo[2] = {v1e, v1o};
                mma_k16(o,     a, be);
                mma_k16(o + 4, a, bo);
                mma_k16(lacc,  a, ones2);
            }
        }
    }

    float inv0 = 1.f / lacc[0], inv1 = 1.f / lacc[2];

    size_t r0 = ((size_t)b*NQ + q0 + wid*16 + g) * ED + hd * HD;
    size_t r1 = r0 + 8 * ED;
    store_hl(g_HPhi, g_HPlo, r0 + t2,     o[0]*inv0, o[1]*inv0);
    store_hl(g_HPhi, g_HPlo, r0 + 8 + t2, o[4]*inv0, o[5]*inv0);
    store_hl(g_HPhi, g_HPlo, r1 + t2,     o[2]*inv1, o[3]*inv1);
    store_hl(g_HPhi, g_HPlo, r1 + 8 + t2, o[6]*inv1, o[7]*inv1);
}

// ======================== launch ========================
extern "C" void kernel_launch(void* const* d_in, const int* in_sizes, int n_in,
                              void* d_out, int out_size)
{
    const float* q = (const float*)d_in[0];
    const float* h = (const float*)d_in[1];
    const void*  mask_raw = d_in[2];
    const float* Wq = (const float*)d_in[3];
    const float* Wk = (const float*)d_in[4];
    const float* Wv = (const float*)d_in[5];
    const float* Wout = (const float*)d_in[6];
    float* out = (float*)d_out;

    __half *Qhi, *Qlo, *Khi, *Vt;
    uint32_t* MB;
    cudaGetSymbolAddress((void**)&Qhi, g_Qhi);
    cudaGetSymbolAddress((void**)&Qlo, g_Qlo);
    cudaGetSymbolAddress((void**)&Khi, g_Khi);
    cudaGetSymbolAddress((void**)&Vt,  g_Vt);
    cudaGetSymbolAddress((void**)&MB,  g_mbits);

    cudaFuncSetAttribute(gemm_mma_kernel,
                         cudaFuncAttributeMaxDynamicSharedMemorySize, GEMM_SMEM);

    split_w_kernel<<<dim3(64, 5), 256>>>(Wq, Wk, Wv, Wout,
                                         (const unsigned int*)mask_raw);
    bitpack_mask_kernel<<<(BB*NQ*32) / 256, 256>>>(mask_raw);

    gemm_mma_kernel<<<dim3(MROWS / 128, 3), 256, GEMM_SMEM>>>(q, h, out, 0);

    dim3 grid(NH, NQ / 128, BB);
    attn_mma_kernel<<<grid, 256>>>(Qhi, Qlo, Khi, Vt, MB);

    gemm_mma_kernel<<<dim3(MROWS / 128, 1), 256, GEMM_SMEM>>>(q, h, out, 3);
}

// round 17
// speedup vs baseline: 1.1827x; 1.0424x over previous
#include <cuda_runtime.h>
#include <cuda_fp16.h>
#include <stdint.h>

#define BB 32
#define NQ 1024
#define GSZ 1024
#define ED 128
#define NH 8
#define HD 16
#define MROWS (BB*NQ)

__device__ __half g_Qhi[(size_t)BB*NH*NQ*HD];
__device__ __half g_Qlo[(size_t)BB*NH*NQ*HD];
__device__ __half g_Khi[(size_t)BB*NH*GSZ*HD];
__device__ __half g_Vt [(size_t)BB*NH*HD*GSZ];   // [b,h,e,g]
__device__ __half g_HPhi[(size_t)MROWS*ED];
__device__ __half g_HPlo[(size_t)MROWS*ED];
__device__ __half g_Whi[4*128*128];              // [mode][n][k]
__device__ __half g_Wlo[4*128*128];
__device__ uint32_t g_mbits[(size_t)BB*NQ*32];
__device__ int g_mdtype;

// ======================== helpers ========================
__device__ __forceinline__ float ex2f(float x) {
    float r; asm("ex2.approx.f32 %0, %1;" : "=f"(r) : "f"(x));
    return r;
}
__device__ __forceinline__ uint32_t packh2_u(__half a, __half b) {
    __half2 h; h.x = a; h.y = b;
    return *(uint32_t*)&h;
}
__device__ __forceinline__ uint32_t packf2(float a, float b) {
    __half2 h = __floats2half2_rn(a, b);
    return *(uint32_t*)&h;
}
__device__ __forceinline__ uint32_t h2u(__half2 h) { return *(uint32_t*)&h; }
__device__ __forceinline__ uint32_t smem_u32(const void* p) {
    uint32_t a;
    asm("{ .reg .u64 t; cvta.to.shared.u64 t, %1; cvt.u32.u64 %0, t; }" : "=r"(a) : "l"(p));
    return a;
}
__device__ __forceinline__ void mma_k16(float* c, const uint32_t* a, const uint32_t* b) {
    asm volatile("mma.sync.aligned.m16n8k16.row.col.f32.f16.f16.f32 "
        "{%0,%1,%2,%3}, {%4,%5,%6,%7}, {%8,%9}, {%0,%1,%2,%3};"
        : "+f"(c[0]), "+f"(c[1]), "+f"(c[2]), "+f"(c[3])
        : "r"(a[0]), "r"(a[1]), "r"(a[2]), "r"(a[3]), "r"(b[0]), "r"(b[1]));
}
#define LDSM_X4(r0, r1, r2, r3, addr) \
    asm volatile("ldmatrix.sync.aligned.m8n8.x4.shared.b16 {%0,%1,%2,%3}, [%4];" \
        : "=r"(r0), "=r"(r1), "=r"(r2), "=r"(r3) : "r"(addr))
#define CP_ASYNC16(dst, src) \
    asm volatile("cp.async.cg.shared.global [%0], [%1], 16;" :: "r"(dst), "l"(src))
#define CP_COMMIT() asm volatile("cp.async.commit_group;" ::: "memory")
#define CP_WAIT0()  asm volatile("cp.async.wait_group 0;" ::: "memory")

// mask bit (0/1 in byte byi of u) -> float init 0.0 / -3.4e38 (2 ALU ops)
__device__ __forceinline__ float mask_prmt(uint32_t u, int byi) {
    return __uint_as_float(__byte_perm(u, 0u, 0x4440 + byi) * 0xFF7FFFFFu);
}

// nonzero-byte -> 4-bit nibble
__device__ __forceinline__ uint32_t nz4(uint32_t w) {
    uint32_t nz = (((w & 0x7F7F7F7Fu) + 0x7F7F7F7Fu) | w) & 0x80808080u;
    return (((nz >> 7) * 0x01020408u) >> 24) & 0xFu;
}

// ======================== W pre-split (+ mask dtype detect slice) ========
__global__ __launch_bounds__(256) void split_w_kernel(
    const float* __restrict__ Wq, const float* __restrict__ Wk,
    const float* __restrict__ Wv, const float* __restrict__ Wout,
    const unsigned int* __restrict__ mask_raw)
{
    int mode = blockIdx.y;
    if (mode == 4) {
        if (blockIdx.x != 0) return;
        __shared__ int sf32, sgt1;
        if (threadIdx.x == 0) { sf32 = 0; sgt1 = 0; }
        __syncthreads();
        for (int i = threadIdx.x; i < 2048; i += blockDim.x) {
            unsigned int w = mask_raw[i];
            if (w == 0x3F800000u) sf32 = 1;
            else if (w > 1u) sgt1 = 1;
        }
        __syncthreads();
        if (threadIdx.x == 0) g_mdtype = sf32 ? 2 : (sgt1 ? 0 : 1);
        return;
    }
    const float* W = (mode == 0) ? Wq : (mode == 1 ? Wk : (mode == 2 ? Wv : Wout));
    int idx = blockIdx.x * 256 + threadIdx.x;
    int n = idx >> 7, k = idx & 127;
    float w = (mode < 3)
        ? W[(size_t)(n >> 4) * (ED * HD) + (size_t)k * HD + (n & 15)]
        : W[(size_t)k * ED + n];
    if (mode == 0) w *= 0.36067376022224085f;   // 0.25 * log2(e)
    __half hh = __float2half_rn(w);
    g_Whi[mode * 16384 + idx] = hh;
    g_Wlo[mode * 16384 + idx] = __float2half_rn(w - __half2float(hh));
}

// ======================== mask bitpack (vectorized) ========================
__global__ __launch_bounds__(256) void bitpack_mask_kernel(const void* __restrict__ m)
{
    int dt = g_mdtype;
    size_t gt = (size_t)blockIdx.x * 256 + threadIdx.x;
    if (dt == 0) {
        if (gt >= (size_t)BB*NQ*32 / 4) return;
        const uint4* p = (const uint4*)m + gt * 8;
        #pragma unroll
        for (int o = 0; o < 4; o++) {
            uint4 a = p[o*2], b = p[o*2+1];
            uint32_t bits = nz4(a.x) | (nz4(a.y) << 4) | (nz4(a.z) << 8) | (nz4(a.w) << 12)
                          | (nz4(b.x) << 16) | (nz4(b.y) << 20)
                          | (nz4(b.z) << 24) | (nz4(b.w) << 28);
            g_mbits[gt * 4 + o] = bits;
        }
    } else {
        const uint4* p = (const uint4*)m + gt * 8;
        uint32_t bits = 0;
        #pragma unroll
        for (int i = 0; i < 8; i++) {
            uint4 v = p[i];
            bits |= (uint32_t)(v.x != 0u) << (i*4)
                  | (uint32_t)(v.y != 0u) << (i*4+1)
                  | (uint32_t)(v.z != 0u) << (i*4+2)
                  | (uint32_t)(v.w != 0u) << (i*4+3);
        }
        g_mbits[gt] = bits;
    }
}

// ======================== pipelined tensor-core GEMM ========================
#define CH 5120
#define GEMM_SMEM (8 * CH * 2)

__global__ __launch_bounds__(256, 2) void gemm_mma_kernel(
    const float* __restrict__ q, const float* __restrict__ h,
    float* __restrict__ out, int mode_base)
{
    extern __shared__ __align__(16) __half dsm[];
    __half* sAhi = dsm;            // [2][CH]
    __half* sAlo = dsm + 2*CH;
    __half* sWhi = dsm + 4*CH;
    __half* sWlo = dsm + 6*CH;

    int mode = mode_base + blockIdx.y;
    const float* A = (mode == 0) ? q : h;

    int tid = threadIdx.x, wid = tid >> 5, lane = tid & 31;
    int row0 = blockIdx.x * 128;
    int wr = wid & 1, wc = wid >> 1;
    int mi = lane >> 3, ri = lane & 7;

    float c[4][4][4] = {};

    uint32_t a_lo = (uint32_t)(((lane & 15) * 40 + (lane >> 4) * 8) * 2);
    uint32_t b_lo = (uint32_t)((((mi >> 1) * 8 + ri) * 40 + (mi & 1) * 8) * 2);
    uint32_t sAhi_b = smem_u32(sAhi), sAlo_b = smem_u32(sAlo);
    uint32_t sWhi_b = smem_u32(sWhi), sWlo_b = smem_u32(sWlo);

    int r_st = tid >> 1, kh_st = (tid & 1) * 16;
    uint32_t st_d = (uint32_t)((r_st * 40 + kh_st) * 2);
    const __half* Whi = g_Whi + mode * 16384;
    const __half* Wlo = g_Wlo + mode * 16384;

    // prologue: chunk 0
    {
        const __half* ws = Whi + r_st * 128 + kh_st;
        const __half* wl = Wlo + r_st * 128 + kh_st;
        CP_ASYNC16(sWhi_b + st_d,      ws);
        CP_ASYNC16(sWhi_b + st_d + 16, ws + 8);
        CP_ASYNC16(sWlo_b + st_d,      wl);
        CP_ASYNC16(sWlo_b + st_d + 16, wl + 8);
        if (mode == 3) {
            const __half* as = g_HPhi + (size_t)(row0 + r_st) * ED + kh_st;
            const __half* al = g_HPlo + (size_t)(row0 + r_st) * ED + kh_st;
            CP_ASYNC16(sAhi_b + st_d,      as);
            CP_ASYNC16(sAhi_b + st_d + 16, as + 8);
            CP_ASYNC16(sAlo_b + st_d,      al);
            CP_ASYNC16(sAlo_b + st_d + 16, al + 8);
        } else {
            const float* ap = A + (size_t)(row0 + r_st) * ED + kh_st;
            #pragma unroll
            for (int j4 = 0; j4 < 4; j4++) {
                float4 v = *(const float4*)(ap + j4 * 4);
                float vv[4] = {v.x, v.y, v.z, v.w};
                __half hi[4], lo[4];
                #pragma unroll
                for (int u = 0; u < 4; u++) {
                    hi[u] = __float2half_rn(vv[u]);
                    lo[u] = __float2half_rn(vv[u] - __half2float(hi[u]));
                }
                *(uint2*)(sAhi + r_st*40 + kh_st + j4*4) = *(uint2*)hi;
                *(uint2*)(sAlo + r_st*40 + kh_st + j4*4) = *(uint2*)lo;
            }
        }
        CP_COMMIT();
    }

    for (int kc = 0; kc < 4; kc++) {
        CP_WAIT0();
        __syncthreads();   // cross-thread visibility of async copies + WAR guard
        int p = kc & 1;
        uint32_t off_p = (uint32_t)(p * CH * 2);

        float4 rA[4];
        if (kc < 3) {
            int pn = p ^ 1;
            uint32_t off_n = (uint32_t)(pn * CH * 2);
            const __half* ws = Whi + r_st * 128 + (kc+1)*32 + kh_st;
            const __half* wl = Wlo + r_st * 128 + (kc+1)*32 + kh_st;
            CP_ASYNC16(sWhi_b + off_n + st_d,      ws);
            CP_ASYNC16(sWhi_b + off_n + st_d + 16, ws + 8);
            CP_ASYNC16(sWlo_b + off_n + st_d,      wl);
            CP_ASYNC16(sWlo_b + off_n + st_d + 16, wl + 8);
            if (mode == 3) {
                const __half* as = g_HPhi + (size_t)(row0 + r_st) * ED + (kc+1)*32 + kh_st;
                const __half* al = g_HPlo + (size_t)(row0 + r_st) * ED + (kc+1)*32 + kh_st;
                CP_ASYNC16(sAhi_b + off_n + st_d,      as);
                CP_ASYNC16(sAhi_b + off_n + st_d + 16, as + 8);
                CP_ASYNC16(sAlo_b + off_n + st_d,      al);
                CP_ASYNC16(sAlo_b + off_n + st_d + 16, al + 8);
            } else {
                const float* ap = A + (size_t)(row0 + r_st) * ED + (kc+1)*32 + kh_st;
                #pragma unroll
                for (int j4 = 0; j4 < 4; j4++) rA[j4] = *(const float4*)(ap + j4 * 4);
            }
            CP_COMMIT();
        }

        #pragma unroll
        for (int ks = 0; ks < 2; ks++) {
            uint32_t koff = (uint32_t)(ks * 32);
            uint32_t bhi[2][4], blo[2][4];
            #pragma unroll
            for (int nb = 0; nb < 2; nb++) {
                uint32_t no = (uint32_t)((wc*32 + nb*16) * 80) + koff + b_lo + off_p;
                LDSM_X4(bhi[nb][0], bhi[nb][1], bhi[nb][2], bhi[nb][3], sWhi_b + no);
                LDSM_X4(blo[nb][0], blo[nb][1], blo[nb][2], blo[nb][3], sWlo_b + no);
            }
            #pragma unroll
            for (int mb = 0; mb < 4; mb++) {
                uint32_t ro = (uint32_t)((wr*64 + mb*16) * 80) + koff + a_lo + off_p;
                uint32_t ahi[4], alo[4];
                LDSM_X4(ahi[0], ahi[1], ahi[2], ahi[3], sAhi_b + ro);
                LDSM_X4(alo[0], alo[1], alo[2], alo[3], sAlo_b + ro);
                #pragma unroll
                for (int ns = 0; ns < 4; ns++) {
                    const uint32_t* bh = &bhi[ns >> 1][(ns & 1) * 2];
                    const uint32_t* bl = &blo[ns >> 1][(ns & 1) * 2];
                    mma_k16(c[mb][ns], ahi, bh);
                    mma_k16(c[mb][ns], alo, bh);
                    mma_k16(c[mb][ns], ahi, bl);
                }
            }
        }

        if (kc < 3 && mode < 3) {
            int pn = p ^ 1;
            #pragma unroll
            for (int j4 = 0; j4 < 4; j4++) {
                float vv[4] = {rA[j4].x, rA[j4].y, rA[j4].z, rA[j4].w};
                __half hi[4], lo[4];
                #pragma unroll
                for (int u = 0; u < 4; u++) {
                    hi[u] = __float2half_rn(vv[u]);
                    lo[u] = __float2half_rn(vv[u] - __half2float(hi[u]));
                }
                *(uint2*)(sAhi + pn*CH + r_st*40 + kh_st + j4*4) = *(uint2*)hi;
                *(uint2*)(sAlo + pn*CH + r_st*40 + kh_st + j4*4) = *(uint2*)lo;
            }
        }
    }

    // epilogue
    int g = lane >> 2, t = lane & 3;
    #pragma unroll
    for (int mb = 0; mb < 4; mb++) {
        int grow = row0 + wr*64 + mb*16 + g;
        #pragma unroll
        for (int ns = 0; ns < 4; ns++) {
            int col = wc*32 + ns*8 + 2*t;
            float* cc = c[mb][ns];
            if (mode == 3) {
                *(float2*)(out + (size_t)grow * ED + col) = make_float2(cc[0], cc[1]);
                *(float2*)(out + (size_t)(grow + 8) * ED + col) = make_float2(cc[2], cc[3]);
            } else {
                int head = col >> 4, e = col & 15;
                int b = grow >> 10, n = grow & 1023;
                if (mode == 2) {
                    __half* vt = g_Vt + ((size_t)(b*NH + head) * 16 + e) * 1024;
                    vt[n]            = __float2half_rn(cc[0]);
                    vt[1024 + n]     = __float2half_rn(cc[1]);
                    vt[n + 8]        = __float2half_rn(cc[2]);
                    vt[1024 + n + 8] = __float2half_rn(cc[3]);
                } else {
                    __half* HI = (mode == 0) ? g_Qhi : g_Khi;
                    size_t base0 = ((size_t)(b*NH + head) * 1024 + n) * 16 + e;
                    size_t base1 = base0 + 8 * 16;
                    __half h0 = __float2half_rn(cc[0]), h1 = __float2half_rn(cc[1]);
                    __half h2 = __float2half_rn(cc[2]), h3 = __float2half_rn(cc[3]);
                    *(uint32_t*)(HI + base0) = packh2_u(h0, h1);
                    *(uint32_t*)(HI + base1) = packh2_u(h2, h3);
                    if (mode == 0) {
                        *(uint32_t*)(g_Qlo + base0) =
                            packf2(cc[0] - __half2float(h0), cc[1] - __half2float(h1));
                        *(uint32_t*)(g_Qlo + base1) =
                            packf2(cc[2] - __half2float(h2), cc[3] - __half2float(h3));
                    }
                }
            }
        }
    }
}

// ======================== flash attention (PRMT mask init) ========
__device__ __forceinline__ void store_hl(__half* HI, __half* LO, size_t off,
                                         float x, float y) {
    __half hx = __float2half_rn(x), hy = __float2half_rn(y);
    *(uint32_t*)(HI + off) = packh2_u(hx, hy);
    *(uint32_t*)(LO + off) = packf2(x - __half2float(hx), y - __half2float(hy));
}

__global__ __launch_bounds__(256, 2) void attn_mma_kernel(
    const __half* __restrict__ Qhi, const __half* __restrict__ Qlo,
    const __half* __restrict__ Khig, const __half* __restrict__ Vtg,
    const uint32_t* __restrict__ Mbits)
{
    __shared__ __align__(16) __half sKhi[2][128*24];
    __shared__ __align__(16) __half sVt [2][16*136];

    int tid = threadIdx.x, wid = tid >> 5, lane = tid & 31;
    int g = lane >> 2, t = lane & 3;
    int hd = blockIdx.x, q0 = blockIdx.y * 128, b = blockIdx.z;

    const __half* Kh = Khig + (size_t)(b*NH+hd) * GSZ * HD;
    const __half* Vg = Vtg  + (size_t)(b*NH+hd) * HD * GSZ;

    int k_row = tid >> 1, k_half = tid & 1;
    int v_e = tid >> 4, v_seg = tid & 15;
    uint32_t dKhi[2], dVt[2];
    #pragma unroll
    for (int bb = 0; bb < 2; bb++) {
        dKhi[bb] = smem_u32(&sKhi[bb][0]) + k_row * 48 + k_half * 16;
        dVt[bb]  = smem_u32(&sVt[bb][0])  + v_e * 272 + v_seg * 16;
    }

    int mi = lane >> 3, ri = lane & 7;
    uint32_t k_lb = (uint32_t)((((mi >> 1) * 8 + ri) * 24 + (mi & 1) * 8) * 2);
    uint32_t v_lb = (uint32_t)((((mi & 1) * 8 + ri) * 136 + (mi >> 1) * 8) * 2);

    {
        const __half* s1 = Kh + (size_t)k_row * 16 + k_half * 8;
        const __half* s3 = Vg + (size_t)v_e * GSZ + v_seg * 8;
        CP_ASYNC16(dKhi[0], s1); CP_ASYNC16(dVt[0], s3);
        CP_COMMIT();
    }

    uint32_t qhi[4], qlo[4];
    {
        size_t qb = ((size_t)(b*NH+hd) * NQ + q0 + wid*16) * 16;
        #pragma unroll
        for (int i = 0; i < 4; i++) {
            int r = g + (i & 1) * 8;
            int cix = 2*t + (i >> 1) * 8;
            qhi[i] = *(const uint32_t*)(Qhi + qb + r*16 + cix);
            qlo[i] = *(const uint32_t*)(Qlo + qb + r*16 + cix);
        }
    }

    int rg0 = q0 + wid*16 + g;
    const uint32_t* mb0p = Mbits + ((size_t)b * NQ + rg0) * 32;
    const uint32_t* mb1p = mb0p + 8 * 32;

    const uint32_t ones2[2] = {0x3C003C00u, 0x3C003C00u};
    float o[8] = {};
    float lacc[4] = {};
    float m0 = -1e30f, m1 = -1e30f;
    int t2 = 2 * t;

    for (int t8 = 0; t8 < 8; t8++) {
        CP_WAIT0();
        __syncthreads();   // visibility of async copies to all threads + WAR guard
        int bb = t8 & 1;

        if (t8 < 7) {
            int k0n = (t8 + 1) * 128;
            const __half* s1 = Kh + (size_t)(k0n + k_row) * 16 + k_half * 8;
            const __half* s3 = Vg + (size_t)v_e * GSZ + k0n + v_seg * 8;
            CP_ASYNC16(dKhi[bb ^ 1], s1); CP_ASYNC16(dVt[bb ^ 1], s3);
            CP_COMMIT();
        }

        uint4 mw0 = *(const uint4*)(mb0p + t8 * 4);
        uint4 mw1 = *(const uint4*)(mb1p + t8 * 4);

        uint32_t khb = smem_u32(&sKhi[bb][0]) + k_lb;
        uint32_t vtb = smem_u32(&sVt[bb][0]) + v_lb;

        #pragma unroll
        for (int hf = 0; hf < 2; hf++) {
            uint32_t wa0 = hf ? mw0.z : mw0.x, wa1 = hf ? mw0.w : mw0.y;
            uint32_t wb0 = hf ? mw1.z : mw1.x, wb1 = hf ? mw1.w : mw1.y;
            uint32_t ya0 = (wa0 >> t2) & 0x01010101u;
            uint32_t ya1 = (wa0 >> (t2 + 1)) & 0x01010101u;
            uint32_t yb0 = (wb0 >> t2) & 0x01010101u;
            uint32_t yb1 = (wb0 >> (t2 + 1)) & 0x01010101u;
            uint32_t za0 = (wa1 >> t2) & 0x01010101u;
            uint32_t za1 = (wa1 >> (t2 + 1)) & 0x01010101u;
            uint32_t zb0 = (wb1 >> t2) & 0x01010101u;
            uint32_t zb1 = (wb1 >> (t2 + 1)) & 0x01010101u;

            // score accumulators initialized with mask bias (0 / -3.4e38)
            float s[8][4];
            #pragma unroll
            for (int kc = 0; kc < 8; kc++) {
                int byi = kc & 3;
                uint32_t u0 = (kc < 4) ? ya0 : za0;
                uint32_t u1 = (kc < 4) ? ya1 : za1;
                uint32_t v0 = (kc < 4) ? yb0 : zb0;
                uint32_t v1 = (kc < 4) ? yb1 : zb1;
                s[kc][0] = mask_prmt(u0, byi);
                s[kc][1] = mask_prmt(u1, byi);
                s[kc][2] = mask_prmt(v0, byi);
                s[kc][3] = mask_prmt(v1, byi);
            }
            #pragma unroll
            for (int j = 0; j < 4; j++) {
                uint32_t kh[4];
                uint32_t off = (uint32_t)((hf*64 + j*16) * 48);
                LDSM_X4(kh[0], kh[1], kh[2], kh[3], khb + off);
                mma_k16(s[2*j],   qhi, kh);
                mma_k16(s[2*j],   qlo, kh);
                mma_k16(s[2*j+1], qhi, kh+2);
                mma_k16(s[2*j+1], qlo, kh+2);
            }
            // row max (masked elements -3.4e38 -> excluded)
            float tm0 = -1e30f, tm1 = -1e30f;
            #pragma unroll
            for (int kc = 0; kc < 8; kc++) {
                tm0 = fmaxf(tm0, fmaxf(s[kc][0], s[kc][1]));
                tm1 = fmaxf(tm1, fmaxf(s[kc][2], s[kc][3]));
            }
            tm0 = fmaxf(tm0, __shfl_xor_sync(0xffffffffu, tm0, 1));
            tm0 = fmaxf(tm0, __shfl_xor_sync(0xffffffffu, tm0, 2));
            tm1 = fmaxf(tm1, __shfl_xor_sync(0xffffffffu, tm1, 1));
            tm1 = fmaxf(tm1, __shfl_xor_sync(0xffffffffu, tm1, 2));

            float mn0 = fmaxf(m0, tm0);
            float mn1 = fmaxf(m1, tm1);
            float f0 = ex2f(m0 - mn0), f1 = ex2f(m1 - mn1);
            m0 = mn0; m1 = mn1;
            o[0] *= f0; o[1] *= f0; o[4] *= f0; o[5] *= f0;
            o[2] *= f1; o[3] *= f1; o[6] *= f1; o[7] *= f1;
            lacc[0] *= f0; lacc[2] *= f1;

            // exp + PV + l
            #pragma unroll
            for (int jj = 0; jj < 4; jj++) {
                uint32_t v0e, v1e, v0o, v1o;
                LDSM_X4(v0e, v1e, v0o, v1o, vtb + (uint32_t)((hf*64 + jj*16) * 2));
                uint32_t a[4];
                #pragma unroll
                for (int q2 = 0; q2 < 2; q2++) {
                    int kc = 2*jj + q2;
                    __half2 d01 = __floats2half2_rn(s[kc][0] - mn0, s[kc][1] - mn0);
                    __half2 d23 = __floats2half2_rn(s[kc][2] - mn1, s[kc][3] - mn1);
                    a[2*q2]     = h2u(h2exp2(d01));
                    a[2*q2 + 1] = h2u(h2exp2(d23));
                }
                uint32_t be[2] = {v0e, v0o};
                uint32_t bo[2] = {v1e, v1o};
                mma_k16(o,     a, be);
                mma_k16(o + 4, a, bo);
                mma_k16(lacc,  a, ones2);
            }
        }
    }

    float inv0 = 1.f / lacc[0], inv1 = 1.f / lacc[2];

    size_t r0 = ((size_t)b*NQ + q0 + wid*16 + g) * ED + hd * HD;
    size_t r1 = r0 + 8 * ED;
    store_hl(g_HPhi, g_HPlo, r0 + t2,     o[0]*inv0, o[1]*inv0);
    store_hl(g_HPhi, g_HPlo, r0 + 8 + t2, o[4]*inv0, o[5]*inv0);
    store_hl(g_HPhi, g_HPlo, r1 + t2,     o[2]*inv1, o[3]*inv1);
    store_hl(g_HPhi, g_HPlo, r1 + 8 + t2, o[6]*inv1, o[7]*inv1);
}

// ======================== launch ========================
extern "C" void kernel_launch(void* const* d_in, const int* in_sizes, int n_in,
                              void* d_out, int out_size)
{
    const float* q = (const float*)d_in[0];
    const float* h = (const float*)d_in[1];
    const void*  mask_raw = d_in[2];
    const float* Wq = (const float*)d_in[3];
    const float* Wk = (const float*)d_in[4];
    const float* Wv = (const float*)d_in[5];
    const float* Wout = (const float*)d_in[6];
    float* out = (float*)d_out;

    __half *Qhi, *Qlo, *Khi, *Vt;
    uint32_t* MB;
    cudaGetSymbolAddress((void**)&Qhi, g_Qhi);
    cudaGetSymbolAddress((void**)&Qlo, g_Qlo);
    cudaGetSymbolAddress((void**)&Khi, g_Khi);
    cudaGetSymbolAddress((void**)&Vt,  g_Vt);
    cudaGetSymbolAddress((void**)&MB,  g_mbits);

    cudaFuncSetAttribute(gemm_mma_kernel,
                         cudaFuncAttributeMaxDynamicSharedMemorySize, GEMM_SMEM);

    split_w_kernel<<<dim3(64, 5), 256>>>(Wq, Wk, Wv, Wout,
                                         (const unsigned int*)mask_raw);
    bitpack_mask_kernel<<<(BB*NQ*32) / 256, 256>>>(mask_raw);

    gemm_mma_kernel<<<dim3(MROWS / 128, 3), 256, GEMM_SMEM>>>(q, h, out, 0);

    dim3 grid(NH, NQ / 128, BB);
    attn_mma_kernel<<<grid, 256>>>(Qhi, Qlo, Khi, Vt, MB);

    gemm_mma_kernel<<<dim3(MROWS / 128, 1), 256, GEMM_SMEM>>>(q, h, out, 3);
}